// round 7
// baseline (speedup 1.0000x reference)
#include <cuda_runtime.h>
#include <mma.h>
#include <math.h>

using namespace nvcuda;

#define SEQ   2048
#define DIMM  2048
#define NH    16
#define QLR   512
#define KVLR  512
#define NOPE  128
#define ROPED 64
#define VHD   128
#define QKHD  192
#define KVBW  4096
#define QW    3072
#define EPSV  1.1920929e-07f
#define ATTN_SCALE 0.07216878364870322f   // 192^-0.5

#define LDS   20
#define GEMM_SMEM (8 * 128 * LDS * 4)     // 81920 B
#define STG_LD 132

// ---------------- scratch ----------------
__device__ float g_qa  [SEQ * QLR];
__device__ float g_q   [SEQ * QW];
__device__ float g_kv  [SEQ * (KVLR + ROPED)];
__device__ float g_kvn [SEQ * KVLR];
__device__ float g_kpe [SEQ * ROPED];
__device__ float g_kvb [SEQ * KVBW];
__device__ float g_k   [SEQ * NH * QKHD];
__device__ float g_sc  [(size_t)NH * SEQ * SEQ];
__device__ float g_att [SEQ * NH * VHD];

__device__ __forceinline__ void split_tf32(float a, float& hi, float& lo) {
    hi = wmma::__float_to_tf32(a);
    lo = wmma::__float_to_tf32(a - hi);
}

__device__ __forceinline__ float blockReduceSum(float v) {
    __shared__ float sh[32];
    int lane = threadIdx.x & 31, wid = threadIdx.x >> 5;
    #pragma unroll
    for (int o = 16; o > 0; o >>= 1) v += __shfl_xor_sync(0xffffffffu, v, o);
    if (lane == 0) sh[wid] = v;
    __syncthreads();
    v = (threadIdx.x < (blockDim.x >> 5)) ? sh[threadIdx.x] : 0.f;
    if (wid == 0) {
        #pragma unroll
        for (int o = 16; o > 0; o >>= 1) v += __shfl_xor_sync(0xffffffffu, v, o);
        if (lane == 0) sh[0] = v;
    }
    __syncthreads();
    return sh[0];
}

__device__ __forceinline__ float blockReduceMax(float v) {
    __shared__ float sh[32];
    int lane = threadIdx.x & 31, wid = threadIdx.x >> 5;
    #pragma unroll
    for (int o = 16; o > 0; o >>= 1) v = fmaxf(v, __shfl_xor_sync(0xffffffffu, v, o));
    if (lane == 0) sh[wid] = v;
    __syncthreads();
    v = (threadIdx.x < (blockDim.x >> 5)) ? sh[threadIdx.x] : -INFINITY;
    if (wid == 0) {
        #pragma unroll
        for (int o = 16; o > 0; o >>= 1) v = fmaxf(v, __shfl_xor_sync(0xffffffffu, v, o));
        if (lane == 0) sh[0] = v;
    }
    __syncthreads();
    return sh[0];
}

// =====================================================================
// 3xTF32 GEMM-NT, 512 threads (16 warps, 32x32 warp tile), double-buffered.
// C[M,N] = alpha * A[M,K] @ W[N,K]^T + bias   (batched over blockIdx.z)
// =====================================================================
template <bool CAUSAL, bool NGUARD>
__global__ __launch_bounds__(512)
void gemm3_nt(const float* __restrict__ A, int lda, long sA,
              const float* __restrict__ W, int ldw, long sW,
              const float* __restrict__ bias,
              float* __restrict__ C, int ldc, long sC,
              int M, int N, int K, float alpha)
{
    const int BM = 128, BK = 16;
    extern __shared__ float sm[];
    const int REG = 128 * LDS;
    float* AH = sm;
    float* AL = sm + 2 * REG;
    float* WH = sm + 4 * REG;
    float* WL = sm + 6 * REG;

    int m0 = blockIdx.y * BM;
    int n0 = blockIdx.x * BM;
    if (CAUSAL && n0 > m0) return;
    long z = blockIdx.z;
    A += z * sA; W += z * sW; C += z * sC;

    int tid = threadIdx.x;
    int wid = tid >> 5;
    int wr = (wid & 3) * 32;
    int wc = (wid >> 2) * 32;
    int lrow = tid >> 2;           // 0..127
    int lc0  = (tid & 3) * 4;      // 0,4,8,12

    const float* pAg = A + (size_t)(m0 + lrow) * lda + lc0;
    const float* pWg = W + (size_t)(n0 + lrow) * ldw + lc0;
    bool wvalid = !NGUARD || (n0 + lrow) < N;

    wmma::fragment<wmma::accumulator, 16, 16, 8, float> acc[2][2];
    #pragma unroll
    for (int i = 0; i < 2; i++)
        #pragma unroll
        for (int j = 0; j < 2; j++) wmma::fill_fragment(acc[i][j], 0.f);

    float ra[4], rw[4];

    {   // prologue tile 0
        float4 a0 = *reinterpret_cast<const float4*>(pAg);
        ra[0]=a0.x; ra[1]=a0.y; ra[2]=a0.z; ra[3]=a0.w;
        if (wvalid) {
            float4 w0 = *reinterpret_cast<const float4*>(pWg);
            rw[0]=w0.x; rw[1]=w0.y; rw[2]=w0.z; rw[3]=w0.w;
        } else { rw[0]=rw[1]=rw[2]=rw[3]=0.f; }
        int off = lrow * LDS + lc0;
        #pragma unroll
        for (int i = 0; i < 4; i++) {
            float hi, lo;
            split_tf32(ra[i], hi, lo); AH[off + i] = hi; AL[off + i] = lo;
            split_tf32(rw[i], hi, lo); WH[off + i] = hi; WL[off + i] = lo;
        }
    }
    __syncthreads();

    int nt = K / BK;
    for (int t = 0; t < nt; t++) {
        int b = (t & 1) * REG;
        if (t + 1 < nt) {
            int k0 = (t + 1) * BK;
            float4 a0 = *reinterpret_cast<const float4*>(pAg + k0);
            ra[0]=a0.x; ra[1]=a0.y; ra[2]=a0.z; ra[3]=a0.w;
            if (wvalid) {
                float4 w0 = *reinterpret_cast<const float4*>(pWg + k0);
                rw[0]=w0.x; rw[1]=w0.y; rw[2]=w0.z; rw[3]=w0.w;
            } else { rw[0]=rw[1]=rw[2]=rw[3]=0.f; }
        }

        #pragma unroll
        for (int kk = 0; kk < BK; kk += 8) {
            wmma::fragment<wmma::matrix_a, 16, 16, 8, wmma::precision::tf32, wmma::row_major> ah[2], al[2];
            wmma::fragment<wmma::matrix_b, 16, 16, 8, wmma::precision::tf32, wmma::col_major> bh[2], bl[2];
            #pragma unroll
            for (int i = 0; i < 2; i++) {
                wmma::load_matrix_sync(ah[i], AH + b + (wr + i * 16) * LDS + kk, LDS);
                wmma::load_matrix_sync(al[i], AL + b + (wr + i * 16) * LDS + kk, LDS);
            }
            #pragma unroll
            for (int j = 0; j < 2; j++) {
                wmma::load_matrix_sync(bh[j], WH + b + (wc + j * 16) * LDS + kk, LDS);
                wmma::load_matrix_sync(bl[j], WL + b + (wc + j * 16) * LDS + kk, LDS);
            }
            #pragma unroll
            for (int i = 0; i < 2; i++)
                #pragma unroll
                for (int j = 0; j < 2; j++) {
                    wmma::mma_sync(acc[i][j], ah[i], bh[j], acc[i][j]);
                    wmma::mma_sync(acc[i][j], al[i], bh[j], acc[i][j]);
                    wmma::mma_sync(acc[i][j], ah[i], bl[j], acc[i][j]);
                }
        }

        if (t + 1 < nt) {
            int nb = ((t + 1) & 1) * REG;
            int off = lrow * LDS + lc0;
            #pragma unroll
            for (int i = 0; i < 4; i++) {
                float hi, lo;
                split_tf32(ra[i], hi, lo); AH[nb + off + i] = hi; AL[nb + off + i] = lo;
                split_tf32(rw[i], hi, lo); WH[nb + off + i] = hi; WL[nb + off + i] = lo;
            }
        }
        __syncthreads();
    }

    // epilogue: stage to smem, coalesced writeback with alpha+bias
    float* stg = sm;
    #pragma unroll
    for (int i = 0; i < 2; i++)
        #pragma unroll
        for (int j = 0; j < 2; j++)
            wmma::store_matrix_sync(stg + (wr + i * 16) * STG_LD + wc + j * 16,
                                    acc[i][j], STG_LD, wmma::mem_row_major);
    __syncthreads();

    int c4 = tid & 31;
    int col = n0 + c4 * 4;
    float4 bv = make_float4(0.f, 0.f, 0.f, 0.f);
    bool cfull = !NGUARD || col + 3 < N;
    if (bias && cfull) {
        bv.x = bias[col]; bv.y = bias[col + 1];
        bv.z = bias[col + 2]; bv.w = bias[col + 3];
    }
    #pragma unroll
    for (int rr = 0; rr < 8; rr++) {
        int row = (tid >> 5) + rr * 16;
        float4 v = *reinterpret_cast<float4*>(stg + row * STG_LD + c4 * 4);
        if (cfull) {
            v.x = v.x * alpha + bv.x;
            v.y = v.y * alpha + bv.y;
            v.z = v.z * alpha + bv.z;
            v.w = v.w * alpha + bv.w;
            *reinterpret_cast<float4*>(C + (size_t)(m0 + row) * ldc + col) = v;
        } else {
            float vv[4] = {v.x, v.y, v.z, v.w};
            #pragma unroll
            for (int e = 0; e < 4; e++)
                if (col + e < N)
                    C[(size_t)(m0 + row) * ldc + col + e] =
                        vv[e] * alpha + (bias ? bias[col + e] : 0.f);
        }
    }
}

// =====================================================================
// 3xTF32 GEMM-NN, 512 threads: C[M,128] = A[M,K] @ B[K,128]
// (batched over z; causal k-limit). Used for probs @ V.
// =====================================================================
template <bool CAUSALK>
__global__ __launch_bounds__(512)
void gemm3_nn(const float* __restrict__ A, int lda, long sA,
              const float* __restrict__ B, int ldb, long sB,
              float* __restrict__ C, int ldc, long sC,
              int M, int K)
{
    const int BM = 128, BK = 16;
    extern __shared__ float sm[];
    const int REG = 128 * LDS;
    float* AH = sm;
    float* AL = sm + 2 * REG;
    float* BH = sm + 4 * REG;
    float* BL = sm + 6 * REG;

    int m0 = blockIdx.y * BM;
    long z = blockIdx.z;
    A += z * sA; B += z * sB; C += z * sC;

    int kmax = CAUSALK ? min(K, m0 + BM) : K;

    int tid = threadIdx.x;
    int wid = tid >> 5;
    int wr = (wid & 3) * 32;
    int wc = (wid >> 2) * 32;
    int lrow = tid >> 2;
    int lc0  = (tid & 3) * 4;
    int bkr  = tid >> 5;           // 0..15 (k row)
    int bc   = tid & 31;           // col base (strided by 32)

    const float* pAg = A + (size_t)(m0 + lrow) * lda + lc0;
    const float* pBg = B + (size_t)bkr * ldb + bc;

    wmma::fragment<wmma::accumulator, 16, 16, 8, float> acc[2][2];
    #pragma unroll
    for (int i = 0; i < 2; i++)
        #pragma unroll
        for (int j = 0; j < 2; j++) wmma::fill_fragment(acc[i][j], 0.f);

    float ra[4], rb[4];

    {   // prologue
        float4 a0 = *reinterpret_cast<const float4*>(pAg);
        ra[0]=a0.x; ra[1]=a0.y; ra[2]=a0.z; ra[3]=a0.w;
        #pragma unroll
        for (int i = 0; i < 4; i++) rb[i] = pBg[32 * i];
        int off = lrow * LDS + lc0;
        #pragma unroll
        for (int i = 0; i < 4; i++) {
            float hi, lo;
            split_tf32(ra[i], hi, lo); AH[off + i] = hi; AL[off + i] = lo;
            split_tf32(rb[i], hi, lo);
            BH[(bc + 32 * i) * LDS + bkr] = hi;
            BL[(bc + 32 * i) * LDS + bkr] = lo;
        }
    }
    __syncthreads();

    int nt = kmax / BK;
    for (int t = 0; t < nt; t++) {
        int b = (t & 1) * REG;
        if (t + 1 < nt) {
            int k0 = (t + 1) * BK;
            float4 a0 = *reinterpret_cast<const float4*>(pAg + k0);
            ra[0]=a0.x; ra[1]=a0.y; ra[2]=a0.z; ra[3]=a0.w;
            const float* p = pBg + (size_t)k0 * ldb;
            #pragma unroll
            for (int i = 0; i < 4; i++) rb[i] = p[32 * i];
        }

        #pragma unroll
        for (int kk = 0; kk < BK; kk += 8) {
            wmma::fragment<wmma::matrix_a, 16, 16, 8, wmma::precision::tf32, wmma::row_major> ah[2], al[2];
            wmma::fragment<wmma::matrix_b, 16, 16, 8, wmma::precision::tf32, wmma::col_major> bh[2], bl[2];
            #pragma unroll
            for (int i = 0; i < 2; i++) {
                wmma::load_matrix_sync(ah[i], AH + b + (wr + i * 16) * LDS + kk, LDS);
                wmma::load_matrix_sync(al[i], AL + b + (wr + i * 16) * LDS + kk, LDS);
            }
            #pragma unroll
            for (int j = 0; j < 2; j++) {
                wmma::load_matrix_sync(bh[j], BH + b + (wc + j * 16) * LDS + kk, LDS);
                wmma::load_matrix_sync(bl[j], BL + b + (wc + j * 16) * LDS + kk, LDS);
            }
            #pragma unroll
            for (int i = 0; i < 2; i++)
                #pragma unroll
                for (int j = 0; j < 2; j++) {
                    wmma::mma_sync(acc[i][j], ah[i], bh[j], acc[i][j]);
                    wmma::mma_sync(acc[i][j], al[i], bh[j], acc[i][j]);
                    wmma::mma_sync(acc[i][j], ah[i], bl[j], acc[i][j]);
                }
        }

        if (t + 1 < nt) {
            int nb = ((t + 1) & 1) * REG;
            int off = lrow * LDS + lc0;
            #pragma unroll
            for (int i = 0; i < 4; i++) {
                float hi, lo;
                split_tf32(ra[i], hi, lo); AH[nb + off + i] = hi; AL[nb + off + i] = lo;
                split_tf32(rb[i], hi, lo);
                BH[nb + (bc + 32 * i) * LDS + bkr] = hi;
                BL[nb + (bc + 32 * i) * LDS + bkr] = lo;
            }
        }
        __syncthreads();
    }

    #pragma unroll
    for (int i = 0; i < 2; i++)
        #pragma unroll
        for (int j = 0; j < 2; j++)
            wmma::store_matrix_sync(C + (size_t)(m0 + wr + i * 16) * ldc + wc + j * 16,
                                    acc[i][j], ldc, wmma::mem_row_major);
}

// ---------------- rmsnorm ----------------
__global__ void rmsnorm_rows(const float* __restrict__ x, const float* __restrict__ w,
                             float* __restrict__ y, int dim)
{
    int row = blockIdx.x;
    const float* xr = x + (size_t)row * dim;
    float ss = 0.f;
    for (int i = threadIdx.x; i < dim; i += blockDim.x) { float v = xr[i]; ss += v * v; }
    ss = blockReduceSum(ss);
    float rinv = rsqrtf(ss / dim + EPSV);
    float* yr = y + (size_t)row * dim;
    for (int i = threadIdx.x; i < dim; i += blockDim.x) yr[i] = xr[i] * rinv * w[i];
}

// ---------------- split kv -> rmsnorm(latent) + rope(k_pe) ----------------
__global__ void kv_norm_rope(const float* __restrict__ kv, const float* __restrict__ w,
                             const float* __restrict__ cosT, const float* __restrict__ sinT,
                             float* __restrict__ kvn, float* __restrict__ kpe)
{
    int s = blockIdx.x;
    const float* kr = kv + (size_t)s * (KVLR + ROPED);
    float ss = 0.f;
    for (int i = threadIdx.x; i < KVLR; i += blockDim.x) { float v = kr[i]; ss += v * v; }
    ss = blockReduceSum(ss);
    float rinv = rsqrtf(ss / KVLR + EPSV);
    for (int i = threadIdx.x; i < KVLR; i += blockDim.x)
        kvn[(size_t)s * KVLR + i] = kr[i] * rinv * w[i];
    if (threadIdx.x < ROPED / 2) {
        int i = threadIdx.x;
        float x0 = kr[KVLR + 2 * i], x1 = kr[KVLR + 2 * i + 1];
        float c = cosT[s * (ROPED / 2) + i], sn = sinT[s * (ROPED / 2) + i];
        kpe[(size_t)s * ROPED + 2 * i]     = x0 * c - x1 * sn;
        kpe[(size_t)s * ROPED + 2 * i + 1] = x0 * sn + x1 * c;
    }
}

// ---------------- rope on q_pe ----------------
__global__ void rope_q(float* __restrict__ q, const float* __restrict__ cosT,
                       const float* __restrict__ sinT)
{
    int s = blockIdx.x;
    int h = threadIdx.x >> 5;
    int i = threadIdx.x & 31;
    float* p = q + (size_t)s * QW + h * QKHD + NOPE + 2 * i;
    float x0 = p[0], x1 = p[1];
    float c = cosT[s * (ROPED / 2) + i], sn = sinT[s * (ROPED / 2) + i];
    p[0] = x0 * c - x1 * sn;
    p[1] = x0 * sn + x1 * c;
}

// ---------------- assemble K ----------------
__global__ void build_k(const float* __restrict__ kvb, const float* __restrict__ kpe,
                        float* __restrict__ k)
{
    int idx = blockIdx.x * blockDim.x + threadIdx.x;
    const int total = SEQ * NH * QKHD;
    if (idx >= total) return;
    int j  = idx % QKHD;
    int sh = idx / QKHD;
    int h  = sh % NH;
    int s  = sh / NH;
    k[idx] = (j < NOPE) ? kvb[(size_t)s * KVBW + h * (NOPE + VHD) + j]
                        : kpe[(size_t)s * ROPED + (j - NOPE)];
}

// ---------------- causal row softmax ----------------
__global__ __launch_bounds__(256)
void softmax_causal(float* __restrict__ scores)
{
    int s = blockIdx.x;
    int h = blockIdx.y;
    float* row = scores + ((size_t)h * SEQ + s) * SEQ;
    int L = s + 1;
    float v[8];
    float mx = -INFINITY;
    #pragma unroll
    for (int k = 0; k < 8; k++) {
        int t = threadIdx.x + k * 256;
        v[k] = (t < L) ? row[t] : -INFINITY;
        mx = fmaxf(mx, v[k]);
    }
    mx = blockReduceMax(mx);
    float sum = 0.f;
    #pragma unroll
    for (int k = 0; k < 8; k++) {
        int t = threadIdx.x + k * 256;
        if (t < L) { v[k] = __expf(v[k] - mx); sum += v[k]; }
        else v[k] = 0.f;
    }
    sum = blockReduceSum(sum);
    float inv = 1.f / sum;
    #pragma unroll
    for (int k = 0; k < 8; k++)
        row[threadIdx.x + k * 256] = v[k] * inv;
}

// =====================================================================
extern "C" void kernel_launch(void* const* d_in, const int* in_sizes, int n_in,
                              void* d_out, int out_size)
{
    const float* x       = (const float*)d_in[0];
    const float* cosT    = (const float*)d_in[2];
    const float* sinT    = (const float*)d_in[3];
    const float* wq_a_w  = (const float*)d_in[5];
    const float* wq_a_b  = (const float*)d_in[6];
    const float* q_nw    = (const float*)d_in[7];
    const float* wq_b_w  = (const float*)d_in[8];
    const float* wq_b_b  = (const float*)d_in[9];
    const float* wkv_a_w = (const float*)d_in[10];
    const float* wkv_a_b = (const float*)d_in[11];
    const float* kv_nw   = (const float*)d_in[12];
    const float* wkv_b_w = (const float*)d_in[13];
    const float* wkv_b_b = (const float*)d_in[14];
    const float* wo_w    = (const float*)d_in[15];
    const float* wo_b    = (const float*)d_in[16];
    float* out = (float*)d_out;

    float *qa, *q, *kv, *kvn, *kpe, *kvb, *k, *sc, *att;
    cudaGetSymbolAddress((void**)&qa,  g_qa);
    cudaGetSymbolAddress((void**)&q,   g_q);
    cudaGetSymbolAddress((void**)&kv,  g_kv);
    cudaGetSymbolAddress((void**)&kvn, g_kvn);
    cudaGetSymbolAddress((void**)&kpe, g_kpe);
    cudaGetSymbolAddress((void**)&kvb, g_kvb);
    cudaGetSymbolAddress((void**)&k,   g_k);
    cudaGetSymbolAddress((void**)&sc,  g_sc);
    cudaGetSymbolAddress((void**)&att, g_att);

    cudaFuncSetAttribute(gemm3_nt<false, false>, cudaFuncAttributeMaxDynamicSharedMemorySize, GEMM_SMEM);
    cudaFuncSetAttribute(gemm3_nt<false, true>,  cudaFuncAttributeMaxDynamicSharedMemorySize, GEMM_SMEM);
    cudaFuncSetAttribute(gemm3_nt<true,  false>, cudaFuncAttributeMaxDynamicSharedMemorySize, GEMM_SMEM);
    cudaFuncSetAttribute(gemm3_nn<true>,         cudaFuncAttributeMaxDynamicSharedMemorySize, GEMM_SMEM);

    // ---- q_a = x @ wq_a^T + b ; rmsnorm ----
    gemm3_nt<false, false><<<dim3(QLR / 128, SEQ / 128, 1), 512, GEMM_SMEM>>>(
        x, DIMM, 0, wq_a_w, DIMM, 0, wq_a_b, qa, QLR, 0, SEQ, QLR, DIMM, 1.f);
    rmsnorm_rows<<<SEQ, 256>>>(qa, q_nw, qa, QLR);

    // ---- q = qa_n @ wq_b^T + b ; rope ----
    gemm3_nt<false, false><<<dim3(QW / 128, SEQ / 128, 1), 512, GEMM_SMEM>>>(
        qa, QLR, 0, wq_b_w, QLR, 0, wq_b_b, q, QW, 0, SEQ, QW, QLR, 1.f);
    rope_q<<<SEQ, NH * 32>>>(q, cosT, sinT);

    // ---- kv = x @ wkv_a^T + b ; split/norm/rope ----
    gemm3_nt<false, true><<<dim3(5, SEQ / 128, 1), 512, GEMM_SMEM>>>(
        x, DIMM, 0, wkv_a_w, DIMM, 0, wkv_a_b, kv, KVLR + ROPED, 0,
        SEQ, KVLR + ROPED, DIMM, 1.f);
    kv_norm_rope<<<SEQ, 256>>>(kv, kv_nw, cosT, sinT, kvn, kpe);

    // ---- kvb = kvn @ wkv_b^T + b ----
    gemm3_nt<false, false><<<dim3(KVBW / 128, SEQ / 128, 1), 512, GEMM_SMEM>>>(
        kvn, KVLR, 0, wkv_b_w, KVLR, 0, wkv_b_b, kvb, KVBW, 0, SEQ, KVBW, KVLR, 1.f);

    // ---- assemble K ----
    build_k<<<(SEQ * NH * QKHD + 255) / 256, 256>>>(kvb, kpe, k);

    // ---- scores (batched over heads, causal tile-skip) ----
    gemm3_nt<true, false><<<dim3(SEQ / 128, SEQ / 128, NH), 512, GEMM_SMEM>>>(
        q, QW, QKHD, k, QW, QKHD, nullptr, sc, SEQ, (long)SEQ * SEQ,
        SEQ, SEQ, QKHD, ATTN_SCALE);

    // ---- softmax ----
    softmax_causal<<<dim3(SEQ, NH), 256>>>(sc);

    // ---- att = probs @ V (batched, causal k-limit) ----
    gemm3_nn<true><<<dim3(1, SEQ / 128, NH), 512, GEMM_SMEM>>>(
        sc, SEQ, (long)SEQ * SEQ,
        kvb + NOPE, KVBW, (long)(NOPE + VHD),
        att, NH * VHD, (long)VHD,
        SEQ, SEQ);

    // ---- out = att @ wo^T + b ----
    gemm3_nt<false, false><<<dim3(DIMM / 128, SEQ / 128, 1), 512, GEMM_SMEM>>>(
        att, NH * VHD, 0, wo_w, NH * VHD, 0, wo_b, out, DIMM, 0,
        SEQ, DIMM, NH * VHD, 1.f);
}

// round 9
// speedup vs baseline: 2.5233x; 2.5233x over previous
#include <cuda_runtime.h>
#include <cuda_bf16.h>
#include <mma.h>
#include <math.h>
#include <cstdint>

using namespace nvcuda;
typedef __nv_bfloat16 bf16;

#define SEQ   2048
#define DIMM  2048
#define NH    16
#define QLR   512
#define KVLR  512
#define NOPE  128
#define ROPED 64
#define VHD   128
#define QKHD  192
#define KVBW  4096
#define QW    3072
#define EPSV  1.1920929e-07f
#define ATTN_SCALE 0.07216878364870322f   // 192^-0.5

#define BKT   32                  // k tile (bf16)
#define LDSB  40                  // smem row stride (elems) for A/W tiles
#define LDSN  136                 // smem row stride for NN B tile
#define REGB  (128 * LDSB)        // elems per (buffer, array)
#define REGN  (32 * LDSN)
#define GEMM_SMEM 81920
#define STG_LD 132

// ---------------- scratch ----------------
__device__ float g_qa  [SEQ * QLR];
__device__ float g_q   [SEQ * QW];
__device__ float g_kv  [SEQ * (KVLR + ROPED)];
__device__ float g_kvn [SEQ * KVLR];
__device__ float g_kpe [SEQ * ROPED];
__device__ float g_kvb [SEQ * KVBW];
__device__ float g_k   [SEQ * NH * QKHD];
__device__ float g_sc  [(size_t)NH * SEQ * SEQ];
__device__ float g_att [SEQ * NH * VHD];

// ---------------- helpers ----------------
__device__ __forceinline__ uint32_t pack2(bf16 a, bf16 b) {
    __nv_bfloat162 t(a, b);
    return *reinterpret_cast<uint32_t*>(&t);
}

__device__ __forceinline__ void ld16(float* r, const float* p) {
    float4 v0 = *reinterpret_cast<const float4*>(p);
    float4 v1 = *reinterpret_cast<const float4*>(p + 4);
    float4 v2 = *reinterpret_cast<const float4*>(p + 8);
    float4 v3 = *reinterpret_cast<const float4*>(p + 12);
    r[0]=v0.x; r[1]=v0.y; r[2]=v0.z; r[3]=v0.w;
    r[4]=v1.x; r[5]=v1.y; r[6]=v1.z; r[7]=v1.w;
    r[8]=v2.x; r[9]=v2.y; r[10]=v2.z; r[11]=v2.w;
    r[12]=v3.x; r[13]=v3.y; r[14]=v3.z; r[15]=v3.w;
}

__device__ __forceinline__ void zero16(float* r) {
    #pragma unroll
    for (int i = 0; i < 16; i++) r[i] = 0.f;
}

// split 16 floats into hi/lo bf16 and store as 2x uint4 each (16B aligned dest)
__device__ __forceinline__ void st_split16(bf16* hi, bf16* lo, const float* r) {
    uint32_t h[8], l[8];
    #pragma unroll
    for (int i = 0; i < 8; i++) {
        float a = r[2 * i], b = r[2 * i + 1];
        bf16 ha = __float2bfloat16(a);
        bf16 hb = __float2bfloat16(b);
        bf16 la = __float2bfloat16(a - __bfloat162float(ha));
        bf16 lb = __float2bfloat16(b - __bfloat162float(hb));
        h[i] = pack2(ha, hb);
        l[i] = pack2(la, lb);
    }
    uint4* ph = reinterpret_cast<uint4*>(hi);
    uint4* pl = reinterpret_cast<uint4*>(lo);
    ph[0] = make_uint4(h[0], h[1], h[2], h[3]);
    ph[1] = make_uint4(h[4], h[5], h[6], h[7]);
    pl[0] = make_uint4(l[0], l[1], l[2], l[3]);
    pl[1] = make_uint4(l[4], l[5], l[6], l[7]);
}

__device__ __forceinline__ float blockReduceSum(float v) {
    __shared__ float sh[32];
    int lane = threadIdx.x & 31, wid = threadIdx.x >> 5;
    #pragma unroll
    for (int o = 16; o > 0; o >>= 1) v += __shfl_xor_sync(0xffffffffu, v, o);
    if (lane == 0) sh[wid] = v;
    __syncthreads();
    v = (threadIdx.x < (blockDim.x >> 5)) ? sh[threadIdx.x] : 0.f;
    if (wid == 0) {
        #pragma unroll
        for (int o = 16; o > 0; o >>= 1) v += __shfl_xor_sync(0xffffffffu, v, o);
        if (lane == 0) sh[0] = v;
    }
    __syncthreads();
    return sh[0];
}

__device__ __forceinline__ float blockReduceMax(float v) {
    __shared__ float sh[32];
    int lane = threadIdx.x & 31, wid = threadIdx.x >> 5;
    #pragma unroll
    for (int o = 16; o > 0; o >>= 1) v = fmaxf(v, __shfl_xor_sync(0xffffffffu, v, o));
    if (lane == 0) sh[wid] = v;
    __syncthreads();
    v = (threadIdx.x < (blockDim.x >> 5)) ? sh[threadIdx.x] : -INFINITY;
    if (wid == 0) {
        #pragma unroll
        for (int o = 16; o > 0; o >>= 1) v = fmaxf(v, __shfl_xor_sync(0xffffffffu, v, o));
        if (lane == 0) sh[0] = v;
    }
    __syncthreads();
    return sh[0];
}

// =====================================================================
// 3xBF16 GEMM-NT: C[M,N] = alpha * A[M,K] @ W[N,K]^T + bias (batched z)
// 256 threads, 8 warps, warp tile 32x64, BK=32, double-buffered.
// =====================================================================
template <bool CAUSAL, bool NGUARD>
__global__ __launch_bounds__(256)
void gemmb_nt(const float* __restrict__ A, int lda, long sA,
              const float* __restrict__ W, int ldw, long sW,
              const float* __restrict__ bias,
              float* __restrict__ C, int ldc, long sC,
              int M, int N, int K, float alpha)
{
    const int BM = 128;
    extern __shared__ float sm[];
    bf16* base = reinterpret_cast<bf16*>(sm);
    bf16* AH = base;
    bf16* AL = base + 2 * REGB;
    bf16* WH = base + 4 * REGB;
    bf16* WL = base + 6 * REGB;

    int m0 = blockIdx.y * BM;
    int n0 = blockIdx.x * BM;
    if (CAUSAL && n0 > m0) return;
    long z = blockIdx.z;
    A += z * sA; W += z * sW; C += z * sC;

    int tid = threadIdx.x;
    int wid = tid >> 5;
    int wr = (wid & 3) * 32;
    int wc = (wid >> 2) * 64;
    int lrow = tid >> 1;            // 0..127
    int lc0  = (tid & 1) * 16;      // 0 or 16

    const float* pAg = A + (size_t)(m0 + lrow) * lda + lc0;
    const float* pWg = W + (size_t)(n0 + lrow) * ldw + lc0;
    bool wvalid = !NGUARD || (n0 + lrow) < N;

    wmma::fragment<wmma::accumulator, 16, 16, 16, float> acc[2][4];
    #pragma unroll
    for (int i = 0; i < 2; i++)
        #pragma unroll
        for (int j = 0; j < 4; j++) wmma::fill_fragment(acc[i][j], 0.f);

    float ra[16], rw[16];
    int soff = lrow * LDSB + lc0;

    {   // prologue
        ld16(ra, pAg);
        if (wvalid) ld16(rw, pWg); else zero16(rw);
        st_split16(AH + soff, AL + soff, ra);
        st_split16(WH + soff, WL + soff, rw);
    }
    __syncthreads();

    int nt = K / BKT;
    for (int t = 0; t < nt; t++) {
        int b = (t & 1) * REGB;
        if (t + 1 < nt) {
            int k0 = (t + 1) * BKT;
            ld16(ra, pAg + k0);
            if (wvalid) ld16(rw, pWg + k0); else zero16(rw);
        }

        #pragma unroll
        for (int kk = 0; kk < BKT; kk += 16) {
            wmma::fragment<wmma::matrix_a, 16, 16, 16, bf16, wmma::row_major> ah[2], al[2];
            wmma::fragment<wmma::matrix_b, 16, 16, 16, bf16, wmma::col_major> bh[4], bl[4];
            #pragma unroll
            for (int i = 0; i < 2; i++) {
                wmma::load_matrix_sync(ah[i], AH + b + (wr + i * 16) * LDSB + kk, LDSB);
                wmma::load_matrix_sync(al[i], AL + b + (wr + i * 16) * LDSB + kk, LDSB);
            }
            #pragma unroll
            for (int j = 0; j < 4; j++) {
                wmma::load_matrix_sync(bh[j], WH + b + (wc + j * 16) * LDSB + kk, LDSB);
                wmma::load_matrix_sync(bl[j], WL + b + (wc + j * 16) * LDSB + kk, LDSB);
            }
            #pragma unroll
            for (int i = 0; i < 2; i++)
                #pragma unroll
                for (int j = 0; j < 4; j++) {
                    wmma::mma_sync(acc[i][j], ah[i], bh[j], acc[i][j]);
                    wmma::mma_sync(acc[i][j], al[i], bh[j], acc[i][j]);
                    wmma::mma_sync(acc[i][j], ah[i], bl[j], acc[i][j]);
                }
        }

        if (t + 1 < nt) {
            int nb = ((t + 1) & 1) * REGB;
            st_split16(AH + nb + soff, AL + nb + soff, ra);
            st_split16(WH + nb + soff, WL + nb + soff, rw);
        }
        __syncthreads();
    }

    // epilogue: stage to smem fp32, coalesced writeback with alpha+bias
    float* stg = sm;
    #pragma unroll
    for (int i = 0; i < 2; i++)
        #pragma unroll
        for (int j = 0; j < 4; j++)
            wmma::store_matrix_sync(stg + (wr + i * 16) * STG_LD + wc + j * 16,
                                    acc[i][j], STG_LD, wmma::mem_row_major);
    __syncthreads();

    int c4 = tid & 31;
    int col = n0 + c4 * 4;
    float4 bv = make_float4(0.f, 0.f, 0.f, 0.f);
    bool cfull = !NGUARD || col + 3 < N;
    if (bias && cfull) {
        bv.x = bias[col]; bv.y = bias[col + 1];
        bv.z = bias[col + 2]; bv.w = bias[col + 3];
    }
    #pragma unroll
    for (int rr = 0; rr < 16; rr++) {
        int row = (tid >> 5) + rr * 8;
        float4 v = *reinterpret_cast<float4*>(stg + row * STG_LD + c4 * 4);
        if (cfull) {
            v.x = v.x * alpha + bv.x;
            v.y = v.y * alpha + bv.y;
            v.z = v.z * alpha + bv.z;
            v.w = v.w * alpha + bv.w;
            *reinterpret_cast<float4*>(C + (size_t)(m0 + row) * ldc + col) = v;
        } else {
            float vv[4] = {v.x, v.y, v.z, v.w};
            #pragma unroll
            for (int e = 0; e < 4; e++)
                if (col + e < N)
                    C[(size_t)(m0 + row) * ldc + col + e] =
                        vv[e] * alpha + (bias ? bias[col + e] : 0.f);
        }
    }
}

// =====================================================================
// 3xBF16 GEMM-NN: C[M,128] = A[M,K] @ B[K,128]   (batched z, causal k-limit)
// B kept row-major in smem (wmma matrix_b row_major) — no transpose.
// =====================================================================
template <bool CAUSALK>
__global__ __launch_bounds__(256)
void gemmb_nn(const float* __restrict__ A, int lda, long sA,
              const float* __restrict__ B, int ldb, long sB,
              float* __restrict__ C, int ldc, long sC,
              int M, int K)
{
    const int BM = 128;
    extern __shared__ float sm[];
    bf16* base = reinterpret_cast<bf16*>(sm);
    bf16* AH = base;
    bf16* AL = base + 2 * REGB;
    bf16* BH = base + 4 * REGB;
    bf16* BL = base + 4 * REGB + 2 * REGN;

    int m0 = blockIdx.y * BM;
    long z = blockIdx.z;
    A += z * sA; B += z * sB; C += z * sC;

    int kmax = CAUSALK ? min(K, m0 + BM) : K;

    int tid = threadIdx.x;
    int wid = tid >> 5;
    int wr = (wid & 3) * 32;
    int wc = (wid >> 2) * 64;
    int lrow = tid >> 1;
    int lc0  = (tid & 1) * 16;
    int bkr  = tid >> 3;            // 0..31 (k row)
    int bn0  = (tid & 7) * 16;      // n col base

    const float* pAg = A + (size_t)(m0 + lrow) * lda + lc0;
    const float* pBg = B + (size_t)bkr * ldb + bn0;

    wmma::fragment<wmma::accumulator, 16, 16, 16, float> acc[2][4];
    #pragma unroll
    for (int i = 0; i < 2; i++)
        #pragma unroll
        for (int j = 0; j < 4; j++) wmma::fill_fragment(acc[i][j], 0.f);

    float ra[16], rb[16];
    int aoff = lrow * LDSB + lc0;
    int boff = bkr * LDSN + bn0;

    {   // prologue
        ld16(ra, pAg);
        ld16(rb, pBg);
        st_split16(AH + aoff, AL + aoff, ra);
        st_split16(BH + boff, BL + boff, rb);
    }
    __syncthreads();

    int nt = kmax / BKT;
    for (int t = 0; t < nt; t++) {
        int ba = (t & 1) * REGB;
        int bb = (t & 1) * REGN;
        if (t + 1 < nt) {
            int k0 = (t + 1) * BKT;
            ld16(ra, pAg + k0);
            ld16(rb, pBg + (size_t)k0 * ldb);
        }

        #pragma unroll
        for (int kk = 0; kk < BKT; kk += 16) {
            wmma::fragment<wmma::matrix_a, 16, 16, 16, bf16, wmma::row_major> ah[2], al[2];
            wmma::fragment<wmma::matrix_b, 16, 16, 16, bf16, wmma::row_major> bh[4], bl[4];
            #pragma unroll
            for (int i = 0; i < 2; i++) {
                wmma::load_matrix_sync(ah[i], AH + ba + (wr + i * 16) * LDSB + kk, LDSB);
                wmma::load_matrix_sync(al[i], AL + ba + (wr + i * 16) * LDSB + kk, LDSB);
            }
            #pragma unroll
            for (int j = 0; j < 4; j++) {
                wmma::load_matrix_sync(bh[j], BH + bb + kk * LDSN + wc + j * 16, LDSN);
                wmma::load_matrix_sync(bl[j], BL + bb + kk * LDSN + wc + j * 16, LDSN);
            }
            #pragma unroll
            for (int i = 0; i < 2; i++)
                #pragma unroll
                for (int j = 0; j < 4; j++) {
                    wmma::mma_sync(acc[i][j], ah[i], bh[j], acc[i][j]);
                    wmma::mma_sync(acc[i][j], al[i], bh[j], acc[i][j]);
                    wmma::mma_sync(acc[i][j], ah[i], bl[j], acc[i][j]);
                }
        }

        if (t + 1 < nt) {
            int na = ((t + 1) & 1) * REGB;
            int nb = ((t + 1) & 1) * REGN;
            st_split16(AH + na + aoff, AL + na + aoff, ra);
            st_split16(BH + nb + boff, BL + nb + boff, rb);
        }
        __syncthreads();
    }

    #pragma unroll
    for (int i = 0; i < 2; i++)
        #pragma unroll
        for (int j = 0; j < 4; j++)
            wmma::store_matrix_sync(C + (size_t)(m0 + wr + i * 16) * ldc + wc + j * 16,
                                    acc[i][j], ldc, wmma::mem_row_major);
}

// ---------------- rmsnorm ----------------
__global__ void rmsnorm_rows(const float* __restrict__ x, const float* __restrict__ w,
                             float* __restrict__ y, int dim)
{
    int row = blockIdx.x;
    const float* xr = x + (size_t)row * dim;
    float ss = 0.f;
    for (int i = threadIdx.x; i < dim; i += blockDim.x) { float v = xr[i]; ss += v * v; }
    ss = blockReduceSum(ss);
    float rinv = rsqrtf(ss / dim + EPSV);
    float* yr = y + (size_t)row * dim;
    for (int i = threadIdx.x; i < dim; i += blockDim.x) yr[i] = xr[i] * rinv * w[i];
}

// ---------------- split kv -> rmsnorm(latent) + rope(k_pe) ----------------
__global__ void kv_norm_rope(const float* __restrict__ kv, const float* __restrict__ w,
                             const float* __restrict__ cosT, const float* __restrict__ sinT,
                             float* __restrict__ kvn, float* __restrict__ kpe)
{
    int s = blockIdx.x;
    const float* kr = kv + (size_t)s * (KVLR + ROPED);
    float ss = 0.f;
    for (int i = threadIdx.x; i < KVLR; i += blockDim.x) { float v = kr[i]; ss += v * v; }
    ss = blockReduceSum(ss);
    float rinv = rsqrtf(ss / KVLR + EPSV);
    for (int i = threadIdx.x; i < KVLR; i += blockDim.x)
        kvn[(size_t)s * KVLR + i] = kr[i] * rinv * w[i];
    if (threadIdx.x < ROPED / 2) {
        int i = threadIdx.x;
        float x0 = kr[KVLR + 2 * i], x1 = kr[KVLR + 2 * i + 1];
        float c = cosT[s * (ROPED / 2) + i], sn = sinT[s * (ROPED / 2) + i];
        kpe[(size_t)s * ROPED + 2 * i]     = x0 * c - x1 * sn;
        kpe[(size_t)s * ROPED + 2 * i + 1] = x0 * sn + x1 * c;
    }
}

// ---------------- rope on q_pe ----------------
__global__ void rope_q(float* __restrict__ q, const float* __restrict__ cosT,
                       const float* __restrict__ sinT)
{
    int s = blockIdx.x;
    int h = threadIdx.x >> 5;
    int i = threadIdx.x & 31;
    float* p = q + (size_t)s * QW + h * QKHD + NOPE + 2 * i;
    float x0 = p[0], x1 = p[1];
    float c = cosT[s * (ROPED / 2) + i], sn = sinT[s * (ROPED / 2) + i];
    p[0] = x0 * c - x1 * sn;
    p[1] = x0 * sn + x1 * c;
}

// ---------------- assemble K ----------------
__global__ void build_k(const float* __restrict__ kvb, const float* __restrict__ kpe,
                        float* __restrict__ k)
{
    int idx = blockIdx.x * blockDim.x + threadIdx.x;
    const int total = SEQ * NH * QKHD;
    if (idx >= total) return;
    int j  = idx % QKHD;
    int sh = idx / QKHD;
    int h  = sh % NH;
    int s  = sh / NH;
    k[idx] = (j < NOPE) ? kvb[(size_t)s * KVBW + h * (NOPE + VHD) + j]
                        : kpe[(size_t)s * ROPED + (j - NOPE)];
}

// ---------------- causal row softmax ----------------
__global__ __launch_bounds__(256)
void softmax_causal(float* __restrict__ scores)
{
    int s = blockIdx.x;
    int h = blockIdx.y;
    float* row = scores + ((size_t)h * SEQ + s) * SEQ;
    int L = s + 1;
    float v[8];
    float mx = -INFINITY;
    #pragma unroll
    for (int k = 0; k < 8; k++) {
        int t = threadIdx.x + k * 256;
        v[k] = (t < L) ? row[t] : -INFINITY;
        mx = fmaxf(mx, v[k]);
    }
    mx = blockReduceMax(mx);
    float sum = 0.f;
    #pragma unroll
    for (int k = 0; k < 8; k++) {
        int t = threadIdx.x + k * 256;
        if (t < L) { v[k] = __expf(v[k] - mx); sum += v[k]; }
        else v[k] = 0.f;
    }
    sum = blockReduceSum(sum);
    float inv = 1.f / sum;
    #pragma unroll
    for (int k = 0; k < 8; k++)
        row[threadIdx.x + k * 256] = v[k] * inv;
}

// =====================================================================
extern "C" void kernel_launch(void* const* d_in, const int* in_sizes, int n_in,
                              void* d_out, int out_size)
{
    const float* x       = (const float*)d_in[0];
    const float* cosT    = (const float*)d_in[2];
    const float* sinT    = (const float*)d_in[3];
    const float* wq_a_w  = (const float*)d_in[5];
    const float* wq_a_b  = (const float*)d_in[6];
    const float* q_nw    = (const float*)d_in[7];
    const float* wq_b_w  = (const float*)d_in[8];
    const float* wq_b_b  = (const float*)d_in[9];
    const float* wkv_a_w = (const float*)d_in[10];
    const float* wkv_a_b = (const float*)d_in[11];
    const float* kv_nw   = (const float*)d_in[12];
    const float* wkv_b_w = (const float*)d_in[13];
    const float* wkv_b_b = (const float*)d_in[14];
    const float* wo_w    = (const float*)d_in[15];
    const float* wo_b    = (const float*)d_in[16];
    float* out = (float*)d_out;

    float *qa, *q, *kv, *kvn, *kpe, *kvb, *k, *sc, *att;
    cudaGetSymbolAddress((void**)&qa,  g_qa);
    cudaGetSymbolAddress((void**)&q,   g_q);
    cudaGetSymbolAddress((void**)&kv,  g_kv);
    cudaGetSymbolAddress((void**)&kvn, g_kvn);
    cudaGetSymbolAddress((void**)&kpe, g_kpe);
    cudaGetSymbolAddress((void**)&kvb, g_kvb);
    cudaGetSymbolAddress((void**)&k,   g_k);
    cudaGetSymbolAddress((void**)&sc,  g_sc);
    cudaGetSymbolAddress((void**)&att, g_att);

    cudaFuncSetAttribute(gemmb_nt<false, false>, cudaFuncAttributeMaxDynamicSharedMemorySize, GEMM_SMEM);
    cudaFuncSetAttribute(gemmb_nt<false, true>,  cudaFuncAttributeMaxDynamicSharedMemorySize, GEMM_SMEM);
    cudaFuncSetAttribute(gemmb_nt<true,  false>, cudaFuncAttributeMaxDynamicSharedMemorySize, GEMM_SMEM);
    cudaFuncSetAttribute(gemmb_nn<true>,         cudaFuncAttributeMaxDynamicSharedMemorySize, GEMM_SMEM);

    // ---- q_a = x @ wq_a^T + b ; rmsnorm ----
    gemmb_nt<false, false><<<dim3(QLR / 128, SEQ / 128, 1), 256, GEMM_SMEM>>>(
        x, DIMM, 0, wq_a_w, DIMM, 0, wq_a_b, qa, QLR, 0, SEQ, QLR, DIMM, 1.f);
    rmsnorm_rows<<<SEQ, 256>>>(qa, q_nw, qa, QLR);

    // ---- q = qa_n @ wq_b^T + b ; rope ----
    gemmb_nt<false, false><<<dim3(QW / 128, SEQ / 128, 1), 256, GEMM_SMEM>>>(
        qa, QLR, 0, wq_b_w, QLR, 0, wq_b_b, q, QW, 0, SEQ, QW, QLR, 1.f);
    rope_q<<<SEQ, NH * 32>>>(q, cosT, sinT);

    // ---- kv = x @ wkv_a^T + b ; split/norm/rope ----
    gemmb_nt<false, true><<<dim3(5, SEQ / 128, 1), 256, GEMM_SMEM>>>(
        x, DIMM, 0, wkv_a_w, DIMM, 0, wkv_a_b, kv, KVLR + ROPED, 0,
        SEQ, KVLR + ROPED, DIMM, 1.f);
    kv_norm_rope<<<SEQ, 256>>>(kv, kv_nw, cosT, sinT, kvn, kpe);

    // ---- kvb = kvn @ wkv_b^T + b ----
    gemmb_nt<false, false><<<dim3(KVBW / 128, SEQ / 128, 1), 256, GEMM_SMEM>>>(
        kvn, KVLR, 0, wkv_b_w, KVLR, 0, wkv_b_b, kvb, KVBW, 0, SEQ, KVBW, KVLR, 1.f);

    // ---- assemble K ----
    build_k<<<(SEQ * NH * QKHD + 255) / 256, 256>>>(kvb, kpe, k);

    // ---- scores (batched over heads, causal tile-skip); K=192 = 6*32 ----
    gemmb_nt<true, false><<<dim3(SEQ / 128, SEQ / 128, NH), 256, GEMM_SMEM>>>(
        q, QW, QKHD, k, QW, QKHD, nullptr, sc, SEQ, (long)SEQ * SEQ,
        SEQ, SEQ, QKHD, ATTN_SCALE);

    // ---- softmax ----
    softmax_causal<<<dim3(SEQ, NH), 256>>>(sc);

    // ---- att = probs @ V (batched, causal k-limit) ----
    gemmb_nn<true><<<dim3(1, SEQ / 128, NH), 256, GEMM_SMEM>>>(
        sc, SEQ, (long)SEQ * SEQ,
        kvb + NOPE, KVBW, (long)(NOPE + VHD),
        att, NH * VHD, (long)VHD,
        SEQ, SEQ);

    // ---- out = att @ wo^T + b ----
    gemmb_nt<false, false><<<dim3(DIMM / 128, SEQ / 128, 1), 256, GEMM_SMEM>>>(
        att, NH * VHD, 0, wo_w, NH * VHD, 0, wo_b, out, DIMM, 0,
        SEQ, DIMM, NH * VHD, 1.f);
}

// round 10
// speedup vs baseline: 2.6637x; 1.0556x over previous
#include <cuda_runtime.h>
#include <cuda_bf16.h>
#include <mma.h>
#include <math.h>
#include <cstdint>

using namespace nvcuda;
typedef __nv_bfloat16 bf16;

#define SEQ   2048
#define DIMM  2048
#define NH    16
#define QLR   512
#define KVLR  512
#define NOPE  128
#define ROPED 64
#define VHD   128
#define QKHD  192
#define KVBW  4096
#define QW    3072
#define EPSV  1.1920929e-07f
#define ATTN_SCALE 0.07216878364870322f   // 192^-0.5

#define BKT   32
#define LDSB  40
#define GEMM_SMEM 81920
#define STG_LD 132

// ---- flash attention tile config ----
#define FBM 64
#define FBN 64
#define FQS 200     // smem stride for 192-wide bf16 tiles
#define FVS 136     // smem stride for 128-wide
#define FSS 72      // smem stride for 64-wide S/P
// smem byte offsets
#define OFF_QH 0
#define OFF_QL 25600
#define OFF_KH 51200
#define OFF_KL 76800
#define OFF_VH 102400
#define OFF_VL 119808
#define OFF_S  137216
#define OFF_PL (137216 + 9216)
#define OFF_O  155648
#define OFF_M  190464
#define OFF_L  190720
#define OFF_C  190976
#define FLASH_SMEM 191232

// ---------------- scratch ----------------
__device__ float g_qa  [SEQ * QLR];
__device__ float g_q   [SEQ * QW];
__device__ float g_kv  [SEQ * (KVLR + ROPED)];
__device__ float g_kvn [SEQ * KVLR];
__device__ float g_kpe [SEQ * ROPED];
__device__ float g_kvb [SEQ * KVBW];
__device__ float g_att [SEQ * NH * VHD];

// ---------------- helpers ----------------
__device__ __forceinline__ uint32_t pack2(bf16 a, bf16 b) {
    __nv_bfloat162 t(a, b);
    return *reinterpret_cast<uint32_t*>(&t);
}

__device__ __forceinline__ void ld16(float* r, const float* p) {
    float4 v0 = *reinterpret_cast<const float4*>(p);
    float4 v1 = *reinterpret_cast<const float4*>(p + 4);
    float4 v2 = *reinterpret_cast<const float4*>(p + 8);
    float4 v3 = *reinterpret_cast<const float4*>(p + 12);
    r[0]=v0.x; r[1]=v0.y; r[2]=v0.z; r[3]=v0.w;
    r[4]=v1.x; r[5]=v1.y; r[6]=v1.z; r[7]=v1.w;
    r[8]=v2.x; r[9]=v2.y; r[10]=v2.z; r[11]=v2.w;
    r[12]=v3.x; r[13]=v3.y; r[14]=v3.z; r[15]=v3.w;
}

__device__ __forceinline__ void zero16(float* r) {
    #pragma unroll
    for (int i = 0; i < 16; i++) r[i] = 0.f;
}

__device__ __forceinline__ void st_split16(bf16* hi, bf16* lo, const float* r) {
    uint32_t h[8], l[8];
    #pragma unroll
    for (int i = 0; i < 8; i++) {
        float a = r[2 * i], b = r[2 * i + 1];
        bf16 ha = __float2bfloat16(a);
        bf16 hb = __float2bfloat16(b);
        bf16 la = __float2bfloat16(a - __bfloat162float(ha));
        bf16 lb = __float2bfloat16(b - __bfloat162float(hb));
        h[i] = pack2(ha, hb);
        l[i] = pack2(la, lb);
    }
    uint4* ph = reinterpret_cast<uint4*>(hi);
    uint4* pl = reinterpret_cast<uint4*>(lo);
    ph[0] = make_uint4(h[0], h[1], h[2], h[3]);
    ph[1] = make_uint4(h[4], h[5], h[6], h[7]);
    pl[0] = make_uint4(l[0], l[1], l[2], l[3]);
    pl[1] = make_uint4(l[4], l[5], l[6], l[7]);
}

__device__ __forceinline__ float blockReduceSum(float v) {
    __shared__ float sh[32];
    int lane = threadIdx.x & 31, wid = threadIdx.x >> 5;
    #pragma unroll
    for (int o = 16; o > 0; o >>= 1) v += __shfl_xor_sync(0xffffffffu, v, o);
    if (lane == 0) sh[wid] = v;
    __syncthreads();
    v = (threadIdx.x < (blockDim.x >> 5)) ? sh[threadIdx.x] : 0.f;
    if (wid == 0) {
        #pragma unroll
        for (int o = 16; o > 0; o >>= 1) v += __shfl_xor_sync(0xffffffffu, v, o);
        if (lane == 0) sh[0] = v;
    }
    __syncthreads();
    return sh[0];
}

// =====================================================================
// 3xBF16 GEMM-NT (identical to R8 passing version)
// =====================================================================
template <bool CAUSAL, bool NGUARD>
__global__ __launch_bounds__(256)
void gemmb_nt(const float* __restrict__ A, int lda, long sA,
              const float* __restrict__ W, int ldw, long sW,
              const float* __restrict__ bias,
              float* __restrict__ C, int ldc, long sC,
              int M, int N, int K, float alpha)
{
    const int BM = 128;
    const int REGB = 128 * LDSB;
    extern __shared__ float sm[];
    bf16* base = reinterpret_cast<bf16*>(sm);
    bf16* AH = base;
    bf16* AL = base + 2 * REGB;
    bf16* WH = base + 4 * REGB;
    bf16* WL = base + 6 * REGB;

    int m0 = blockIdx.y * BM;
    int n0 = blockIdx.x * BM;
    if (CAUSAL && n0 > m0) return;
    long z = blockIdx.z;
    A += z * sA; W += z * sW; C += z * sC;

    int tid = threadIdx.x;
    int wid = tid >> 5;
    int wr = (wid & 3) * 32;
    int wc = (wid >> 2) * 64;
    int lrow = tid >> 1;
    int lc0  = (tid & 1) * 16;

    const float* pAg = A + (size_t)(m0 + lrow) * lda + lc0;
    const float* pWg = W + (size_t)(n0 + lrow) * ldw + lc0;
    bool wvalid = !NGUARD || (n0 + lrow) < N;

    wmma::fragment<wmma::accumulator, 16, 16, 16, float> acc[2][4];
    #pragma unroll
    for (int i = 0; i < 2; i++)
        #pragma unroll
        for (int j = 0; j < 4; j++) wmma::fill_fragment(acc[i][j], 0.f);

    float ra[16], rw[16];
    int soff = lrow * LDSB + lc0;

    {
        ld16(ra, pAg);
        if (wvalid) ld16(rw, pWg); else zero16(rw);
        st_split16(AH + soff, AL + soff, ra);
        st_split16(WH + soff, WL + soff, rw);
    }
    __syncthreads();

    int nt = K / BKT;
    for (int t = 0; t < nt; t++) {
        int b = (t & 1) * REGB;
        if (t + 1 < nt) {
            int k0 = (t + 1) * BKT;
            ld16(ra, pAg + k0);
            if (wvalid) ld16(rw, pWg + k0); else zero16(rw);
        }

        #pragma unroll
        for (int kk = 0; kk < BKT; kk += 16) {
            wmma::fragment<wmma::matrix_a, 16, 16, 16, bf16, wmma::row_major> ah[2], al[2];
            wmma::fragment<wmma::matrix_b, 16, 16, 16, bf16, wmma::col_major> bh[4], bl[4];
            #pragma unroll
            for (int i = 0; i < 2; i++) {
                wmma::load_matrix_sync(ah[i], AH + b + (wr + i * 16) * LDSB + kk, LDSB);
                wmma::load_matrix_sync(al[i], AL + b + (wr + i * 16) * LDSB + kk, LDSB);
            }
            #pragma unroll
            for (int j = 0; j < 4; j++) {
                wmma::load_matrix_sync(bh[j], WH + b + (wc + j * 16) * LDSB + kk, LDSB);
                wmma::load_matrix_sync(bl[j], WL + b + (wc + j * 16) * LDSB + kk, LDSB);
            }
            #pragma unroll
            for (int i = 0; i < 2; i++)
                #pragma unroll
                for (int j = 0; j < 4; j++) {
                    wmma::mma_sync(acc[i][j], ah[i], bh[j], acc[i][j]);
                    wmma::mma_sync(acc[i][j], al[i], bh[j], acc[i][j]);
                    wmma::mma_sync(acc[i][j], ah[i], bl[j], acc[i][j]);
                }
        }

        if (t + 1 < nt) {
            int nb = ((t + 1) & 1) * REGB;
            st_split16(AH + nb + soff, AL + nb + soff, ra);
            st_split16(WH + nb + soff, WL + nb + soff, rw);
        }
        __syncthreads();
    }

    float* stg = sm;
    #pragma unroll
    for (int i = 0; i < 2; i++)
        #pragma unroll
        for (int j = 0; j < 4; j++)
            wmma::store_matrix_sync(stg + (wr + i * 16) * STG_LD + wc + j * 16,
                                    acc[i][j], STG_LD, wmma::mem_row_major);
    __syncthreads();

    int c4 = tid & 31;
    int col = n0 + c4 * 4;
    float4 bv = make_float4(0.f, 0.f, 0.f, 0.f);
    bool cfull = !NGUARD || col + 3 < N;
    if (bias && cfull) {
        bv.x = bias[col]; bv.y = bias[col + 1];
        bv.z = bias[col + 2]; bv.w = bias[col + 3];
    }
    #pragma unroll
    for (int rr = 0; rr < 16; rr++) {
        int row = (tid >> 5) + rr * 8;
        float4 v = *reinterpret_cast<float4*>(stg + row * STG_LD + c4 * 4);
        if (cfull) {
            v.x = v.x * alpha + bv.x;
            v.y = v.y * alpha + bv.y;
            v.z = v.z * alpha + bv.z;
            v.w = v.w * alpha + bv.w;
            *reinterpret_cast<float4*>(C + (size_t)(m0 + row) * ldc + col) = v;
        } else {
            float vv[4] = {v.x, v.y, v.z, v.w};
            #pragma unroll
            for (int e = 0; e < 4; e++)
                if (col + e < N)
                    C[(size_t)(m0 + row) * ldc + col + e] =
                        vv[e] * alpha + (bias ? bias[col + e] : 0.f);
        }
    }
}

// =====================================================================
// Fused flash attention (causal), 3xBF16 wmma, online softmax.
// grid = (NH, SEQ/FBM), 256 threads.
// =====================================================================
__global__ __launch_bounds__(256)
void flash_attn(const float* __restrict__ q,     // [SEQ][QW]
                const float* __restrict__ kvb,   // [SEQ][KVBW]
                const float* __restrict__ kpe,   // [SEQ][ROPED]
                float* __restrict__ att)         // [SEQ][NH*VHD]
{
    extern __shared__ char smemc[];
    bf16*  QH = (bf16*)(smemc + OFF_QH);
    bf16*  QL = (bf16*)(smemc + OFF_QL);
    bf16*  KH = (bf16*)(smemc + OFF_KH);
    bf16*  KL = (bf16*)(smemc + OFF_KL);
    bf16*  VH = (bf16*)(smemc + OFF_VH);
    bf16*  VL = (bf16*)(smemc + OFF_VL);
    float* S  = (float*)(smemc + OFF_S);
    bf16*  PH = (bf16*)(smemc + OFF_S);     // union with S (phase-separated)
    bf16*  PL = (bf16*)(smemc + OFF_PL);
    float* O  = (float*)(smemc + OFF_O);
    float* mv = (float*)(smemc + OFF_M);
    float* lv = (float*)(smemc + OFF_L);
    float* cvv= (float*)(smemc + OFF_C);

    int h  = blockIdx.x;
    int mq = gridDim.y - 1 - blockIdx.y;   // heavy blocks scheduled first
    int m0 = mq * FBM;
    int tid = threadIdx.x;
    int wid = tid >> 5;
    int r4  = tid >> 2;        // 0..63 row owned
    int q4  = tid & 3;

    // ---- load Q tile (pre-scaled), init O/m/l ----
    #pragma unroll
    for (int it = 0; it < 3; it++) {
        int col = q4 * 16 + it * 64;
        float rr[16];
        ld16(rr, q + (size_t)(m0 + r4) * QW + h * QKHD + col);
        #pragma unroll
        for (int i = 0; i < 16; i++) rr[i] *= ATTN_SCALE;
        st_split16(QH + r4 * FQS + col, QL + r4 * FQS + col, rr);
    }
    for (int i = tid; i < FBM * FVS; i += 256) O[i] = 0.f;
    if (tid < FBM) { mv[tid] = -INFINITY; lv[tid] = 0.f; }
    __syncthreads();

    for (int jt = 0; jt <= mq; jt++) {
        int j0 = jt * FBN;

        // ---- load K (from kvb nope + kpe rope) and V tiles ----
        #pragma unroll
        for (int it = 0; it < 3; it++) {
            int col = q4 * 16 + it * 64;
            const float* src = (col < NOPE)
                ? (kvb + (size_t)(j0 + r4) * KVBW + h * (NOPE + VHD) + col)
                : (kpe + (size_t)(j0 + r4) * ROPED + (col - NOPE));
            float rr[16];
            ld16(rr, src);
            st_split16(KH + r4 * FQS + col, KL + r4 * FQS + col, rr);
        }
        #pragma unroll
        for (int it = 0; it < 2; it++) {
            int col = q4 * 16 + it * 64;
            float rr[16];
            ld16(rr, kvb + (size_t)(j0 + r4) * KVBW + h * (NOPE + VHD) + NOPE + col);
            st_split16(VH + r4 * FVS + col, VL + r4 * FVS + col, rr);
        }
        __syncthreads();

        // ---- S = Q @ K^T (scaled) ----
        {
            int wr = (wid >> 1) * 16;
            int wc = (wid & 1) * 32;
            wmma::fragment<wmma::accumulator, 16, 16, 16, float> sacc[2];
            #pragma unroll
            for (int j = 0; j < 2; j++) wmma::fill_fragment(sacc[j], 0.f);
            #pragma unroll
            for (int kk = 0; kk < QKHD; kk += 16) {
                wmma::fragment<wmma::matrix_a, 16, 16, 16, bf16, wmma::row_major> ah, al;
                wmma::fragment<wmma::matrix_b, 16, 16, 16, bf16, wmma::col_major> bh, bl;
                wmma::load_matrix_sync(ah, QH + wr * FQS + kk, FQS);
                wmma::load_matrix_sync(al, QL + wr * FQS + kk, FQS);
                #pragma unroll
                for (int j = 0; j < 2; j++) {
                    wmma::load_matrix_sync(bh, KH + (wc + j * 16) * FQS + kk, FQS);
                    wmma::load_matrix_sync(bl, KL + (wc + j * 16) * FQS + kk, FQS);
                    wmma::mma_sync(sacc[j], ah, bh, sacc[j]);
                    wmma::mma_sync(sacc[j], al, bh, sacc[j]);
                    wmma::mma_sync(sacc[j], ah, bl, sacc[j]);
                }
            }
            #pragma unroll
            for (int j = 0; j < 2; j++)
                wmma::store_matrix_sync(S + wr * FSS + wc + j * 16, sacc[j],
                                        FSS, wmma::mem_row_major);
        }
        __syncthreads();

        // ---- online softmax (row r4, cols q4*16..+16) ----
        float p[16];
        {
            bool diag = (jt == mq);
            float s[16];
            const float* Sr = S + r4 * FSS + q4 * 16;
            #pragma unroll
            for (int i = 0; i < 16; i++) s[i] = Sr[i];
            if (diag) {
                #pragma unroll
                for (int i = 0; i < 16; i++)
                    if (q4 * 16 + i > r4) s[i] = -INFINITY;
            }
            float rmax = s[0];
            #pragma unroll
            for (int i = 1; i < 16; i++) rmax = fmaxf(rmax, s[i]);
            rmax = fmaxf(rmax, __shfl_xor_sync(0xffffffffu, rmax, 1));
            rmax = fmaxf(rmax, __shfl_xor_sync(0xffffffffu, rmax, 2));
            float mo = mv[r4];
            float mn = fmaxf(mo, rmax);
            float ps = 0.f;
            #pragma unroll
            for (int i = 0; i < 16; i++) { p[i] = __expf(s[i] - mn); ps += p[i]; }
            ps += __shfl_xor_sync(0xffffffffu, ps, 1);
            ps += __shfl_xor_sync(0xffffffffu, ps, 2);
            float c = __expf(mo - mn);
            if (q4 == 0) {
                mv[r4] = mn;
                lv[r4] = c * lv[r4] + ps;
                cvv[r4] = c;
            }
        }
        __syncthreads();   // all S reads done before P overwrites the union

        // ---- write P (hi/lo) + rescale O ----
        st_split16(PH + r4 * FSS + q4 * 16, PL + r4 * FSS + q4 * 16, p);
        {
            float c = cvv[r4];
            float4* Or = reinterpret_cast<float4*>(O + r4 * FVS + q4 * 32);
            #pragma unroll
            for (int i = 0; i < 8; i++) {
                float4 v = Or[i];
                v.x *= c; v.y *= c; v.z *= c; v.w *= c;
                Or[i] = v;
            }
        }
        __syncthreads();

        // ---- O += P @ V ----
        {
            int wr = (wid >> 1) * 16;
            int wc = (wid & 1) * 64;
            wmma::fragment<wmma::accumulator, 16, 16, 16, float> oacc[4];
            #pragma unroll
            for (int j = 0; j < 4; j++)
                wmma::load_matrix_sync(oacc[j], O + wr * FVS + wc + j * 16,
                                       FVS, wmma::mem_row_major);
            #pragma unroll
            for (int kk = 0; kk < FBN; kk += 16) {
                wmma::fragment<wmma::matrix_a, 16, 16, 16, bf16, wmma::row_major> pa, pl2;
                wmma::fragment<wmma::matrix_b, 16, 16, 16, bf16, wmma::row_major> vb, vbl;
                wmma::load_matrix_sync(pa,  PH + wr * FSS + kk, FSS);
                wmma::load_matrix_sync(pl2, PL + wr * FSS + kk, FSS);
                #pragma unroll
                for (int j = 0; j < 4; j++) {
                    wmma::load_matrix_sync(vb,  VH + kk * FVS + wc + j * 16, FVS);
                    wmma::load_matrix_sync(vbl, VL + kk * FVS + wc + j * 16, FVS);
                    wmma::mma_sync(oacc[j], pa,  vb,  oacc[j]);
                    wmma::mma_sync(oacc[j], pl2, vb,  oacc[j]);
                    wmma::mma_sync(oacc[j], pa,  vbl, oacc[j]);
                }
            }
            #pragma unroll
            for (int j = 0; j < 4; j++)
                wmma::store_matrix_sync(O + wr * FVS + wc + j * 16, oacc[j],
                                        FVS, wmma::mem_row_major);
        }
        __syncthreads();
    }

    // ---- epilogue: normalize and write out ----
    {
        float inv = 1.f / lv[r4];
        const float4* Or = reinterpret_cast<const float4*>(O + r4 * FVS + q4 * 32);
        float4* outp = reinterpret_cast<float4*>(
            att + (size_t)(m0 + r4) * (NH * VHD) + h * VHD + q4 * 32);
        #pragma unroll
        for (int i = 0; i < 8; i++) {
            float4 v = Or[i];
            v.x *= inv; v.y *= inv; v.z *= inv; v.w *= inv;
            outp[i] = v;
        }
    }
}

// ---------------- rmsnorm ----------------
__global__ void rmsnorm_rows(const float* __restrict__ x, const float* __restrict__ w,
                             float* __restrict__ y, int dim)
{
    int row = blockIdx.x;
    const float* xr = x + (size_t)row * dim;
    float ss = 0.f;
    for (int i = threadIdx.x; i < dim; i += blockDim.x) { float v = xr[i]; ss += v * v; }
    ss = blockReduceSum(ss);
    float rinv = rsqrtf(ss / dim + EPSV);
    float* yr = y + (size_t)row * dim;
    for (int i = threadIdx.x; i < dim; i += blockDim.x) yr[i] = xr[i] * rinv * w[i];
}

// ---------------- split kv -> rmsnorm(latent) + rope(k_pe) ----------------
__global__ void kv_norm_rope(const float* __restrict__ kv, const float* __restrict__ w,
                             const float* __restrict__ cosT, const float* __restrict__ sinT,
                             float* __restrict__ kvn, float* __restrict__ kpe)
{
    int s = blockIdx.x;
    const float* kr = kv + (size_t)s * (KVLR + ROPED);
    float ss = 0.f;
    for (int i = threadIdx.x; i < KVLR; i += blockDim.x) { float v = kr[i]; ss += v * v; }
    ss = blockReduceSum(ss);
    float rinv = rsqrtf(ss / KVLR + EPSV);
    for (int i = threadIdx.x; i < KVLR; i += blockDim.x)
        kvn[(size_t)s * KVLR + i] = kr[i] * rinv * w[i];
    if (threadIdx.x < ROPED / 2) {
        int i = threadIdx.x;
        float x0 = kr[KVLR + 2 * i], x1 = kr[KVLR + 2 * i + 1];
        float c = cosT[s * (ROPED / 2) + i], sn = sinT[s * (ROPED / 2) + i];
        kpe[(size_t)s * ROPED + 2 * i]     = x0 * c - x1 * sn;
        kpe[(size_t)s * ROPED + 2 * i + 1] = x0 * sn + x1 * c;
    }
}

// ---------------- rope on q_pe ----------------
__global__ void rope_q(float* __restrict__ q, const float* __restrict__ cosT,
                       const float* __restrict__ sinT)
{
    int s = blockIdx.x;
    int h = threadIdx.x >> 5;
    int i = threadIdx.x & 31;
    float* p = q + (size_t)s * QW + h * QKHD + NOPE + 2 * i;
    float x0 = p[0], x1 = p[1];
    float c = cosT[s * (ROPED / 2) + i], sn = sinT[s * (ROPED / 2) + i];
    p[0] = x0 * c - x1 * sn;
    p[1] = x0 * sn + x1 * c;
}

// =====================================================================
extern "C" void kernel_launch(void* const* d_in, const int* in_sizes, int n_in,
                              void* d_out, int out_size)
{
    const float* x       = (const float*)d_in[0];
    const float* cosT    = (const float*)d_in[2];
    const float* sinT    = (const float*)d_in[3];
    const float* wq_a_w  = (const float*)d_in[5];
    const float* wq_a_b  = (const float*)d_in[6];
    const float* q_nw    = (const float*)d_in[7];
    const float* wq_b_w  = (const float*)d_in[8];
    const float* wq_b_b  = (const float*)d_in[9];
    const float* wkv_a_w = (const float*)d_in[10];
    const float* wkv_a_b = (const float*)d_in[11];
    const float* kv_nw   = (const float*)d_in[12];
    const float* wkv_b_w = (const float*)d_in[13];
    const float* wkv_b_b = (const float*)d_in[14];
    const float* wo_w    = (const float*)d_in[15];
    const float* wo_b    = (const float*)d_in[16];
    float* out = (float*)d_out;

    float *qa, *q, *kv, *kvn, *kpe, *kvb, *att;
    cudaGetSymbolAddress((void**)&qa,  g_qa);
    cudaGetSymbolAddress((void**)&q,   g_q);
    cudaGetSymbolAddress((void**)&kv,  g_kv);
    cudaGetSymbolAddress((void**)&kvn, g_kvn);
    cudaGetSymbolAddress((void**)&kpe, g_kpe);
    cudaGetSymbolAddress((void**)&kvb, g_kvb);
    cudaGetSymbolAddress((void**)&att, g_att);

    cudaFuncSetAttribute(gemmb_nt<false, false>, cudaFuncAttributeMaxDynamicSharedMemorySize, GEMM_SMEM);
    cudaFuncSetAttribute(gemmb_nt<false, true>,  cudaFuncAttributeMaxDynamicSharedMemorySize, GEMM_SMEM);
    cudaFuncSetAttribute(flash_attn,             cudaFuncAttributeMaxDynamicSharedMemorySize, FLASH_SMEM);

    // ---- q_a = x @ wq_a^T + b ; rmsnorm ----
    gemmb_nt<false, false><<<dim3(QLR / 128, SEQ / 128, 1), 256, GEMM_SMEM>>>(
        x, DIMM, 0, wq_a_w, DIMM, 0, wq_a_b, qa, QLR, 0, SEQ, QLR, DIMM, 1.f);
    rmsnorm_rows<<<SEQ, 256>>>(qa, q_nw, qa, QLR);

    // ---- q = qa_n @ wq_b^T + b ; rope ----
    gemmb_nt<false, false><<<dim3(QW / 128, SEQ / 128, 1), 256, GEMM_SMEM>>>(
        qa, QLR, 0, wq_b_w, QLR, 0, wq_b_b, q, QW, 0, SEQ, QW, QLR, 1.f);
    rope_q<<<SEQ, NH * 32>>>(q, cosT, sinT);

    // ---- kv = x @ wkv_a^T + b ; split/norm/rope ----
    gemmb_nt<false, true><<<dim3(5, SEQ / 128, 1), 256, GEMM_SMEM>>>(
        x, DIMM, 0, wkv_a_w, DIMM, 0, wkv_a_b, kv, KVLR + ROPED, 0,
        SEQ, KVLR + ROPED, DIMM, 1.f);
    kv_norm_rope<<<SEQ, 256>>>(kv, kv_nw, cosT, sinT, kvn, kpe);

    // ---- kvb = kvn @ wkv_b^T + b ----
    gemmb_nt<false, false><<<dim3(KVBW / 128, SEQ / 128, 1), 256, GEMM_SMEM>>>(
        kvn, KVLR, 0, wkv_b_w, KVLR, 0, wkv_b_b, kvb, KVBW, 0, SEQ, KVBW, KVLR, 1.f);

    // ---- fused flash attention ----
    flash_attn<<<dim3(NH, SEQ / FBM), 256, FLASH_SMEM>>>(q, kvb, kpe, att);

    // ---- out = att @ wo^T + b ----
    gemmb_nt<false, false><<<dim3(DIMM / 128, SEQ / 128, 1), 256, GEMM_SMEM>>>(
        att, NH * VHD, 0, wo_w, NH * VHD, 0, wo_b, out, DIMM, 0,
        SEQ, DIMM, NH * VHD, 1.f);
}

// round 17
// speedup vs baseline: 3.0733x; 1.1538x over previous
#include <cuda_runtime.h>
#include <cuda_bf16.h>
#include <mma.h>
#include <math.h>
#include <cstdint>

using namespace nvcuda;
typedef __nv_bfloat16 bf16;

#define SEQ   2048
#define DIMM  2048
#define NH    16
#define QLR   512
#define KVLR  512
#define NOPE  128
#define ROPED 64
#define VHD   128
#define QKHD  192
#define KVBW  4096
#define QW    3072
#define EPSV  1.1920929e-07f
#define ATTN_SCALE 0.07216878364870322f   // 192^-0.5

#define BKT   32
#define LDSB  40
#define GEMM_SMEM 81920
#define STG_LD 132

// ---- flash attention tile config ----
#define FBM 64
#define FBN 64
#define FQS 200
#define FVS 136
#define FSS 72
#define OFF_QH 0
#define OFF_QL 25600
#define OFF_KH 51200
#define OFF_KL 76800
#define OFF_VH 102400
#define OFF_VL 119808
#define OFF_S  137216
#define OFF_PL (137216 + 9216)
#define OFF_O  155648
#define OFF_M  190464
#define OFF_L  190720
#define OFF_C  190976
#define FLASH_SMEM 191232

// ---------------- scratch ----------------
__device__ float g_qa  [SEQ * QLR];
__device__ float g_q   [SEQ * QW];
__device__ float g_kv  [SEQ * (KVLR + ROPED)];
__device__ float g_kvn [SEQ * KVLR];
__device__ float g_kpe [SEQ * ROPED];
__device__ float g_kvb [SEQ * KVBW];
__device__ float g_att [SEQ * NH * VHD];

// ---------------- helpers ----------------
__device__ __forceinline__ uint32_t pack2(bf16 a, bf16 b) {
    __nv_bfloat162 t(a, b);
    return *reinterpret_cast<uint32_t*>(&t);
}

__device__ __forceinline__ void ld16(float* r, const float* p) {
    float4 v0 = *reinterpret_cast<const float4*>(p);
    float4 v1 = *reinterpret_cast<const float4*>(p + 4);
    float4 v2 = *reinterpret_cast<const float4*>(p + 8);
    float4 v3 = *reinterpret_cast<const float4*>(p + 12);
    r[0]=v0.x; r[1]=v0.y; r[2]=v0.z; r[3]=v0.w;
    r[4]=v1.x; r[5]=v1.y; r[6]=v1.z; r[7]=v1.w;
    r[8]=v2.x; r[9]=v2.y; r[10]=v2.z; r[11]=v2.w;
    r[12]=v3.x; r[13]=v3.y; r[14]=v3.z; r[15]=v3.w;
}

__device__ __forceinline__ void zero16(float* r) {
    #pragma unroll
    for (int i = 0; i < 16; i++) r[i] = 0.f;
}

__device__ __forceinline__ void st_split16(bf16* hi, bf16* lo, const float* r) {
    uint32_t h[8], l[8];
    #pragma unroll
    for (int i = 0; i < 8; i++) {
        float a = r[2 * i], b = r[2 * i + 1];
        bf16 ha = __float2bfloat16(a);
        bf16 hb = __float2bfloat16(b);
        bf16 la = __float2bfloat16(a - __bfloat162float(ha));
        bf16 lb = __float2bfloat16(b - __bfloat162float(hb));
        h[i] = pack2(ha, hb);
        l[i] = pack2(la, lb);
    }
    uint4* ph = reinterpret_cast<uint4*>(hi);
    uint4* pl = reinterpret_cast<uint4*>(lo);
    ph[0] = make_uint4(h[0], h[1], h[2], h[3]);
    ph[1] = make_uint4(h[4], h[5], h[6], h[7]);
    pl[0] = make_uint4(l[0], l[1], l[2], l[3]);
    pl[1] = make_uint4(l[4], l[5], l[6], l[7]);
}

__device__ __forceinline__ float blockReduceSum(float v) {
    __shared__ float sh[32];
    int lane = threadIdx.x & 31, wid = threadIdx.x >> 5;
    #pragma unroll
    for (int o = 16; o > 0; o >>= 1) v += __shfl_xor_sync(0xffffffffu, v, o);
    if (lane == 0) sh[wid] = v;
    __syncthreads();
    v = (threadIdx.x < (blockDim.x >> 5)) ? sh[threadIdx.x] : 0.f;
    if (wid == 0) {
        #pragma unroll
        for (int o = 16; o > 0; o >>= 1) v += __shfl_xor_sync(0xffffffffu, v, o);
        if (lane == 0) sh[0] = v;
    }
    __syncthreads();
    return sh[0];
}

// =====================================================================
// Shared GEMM body: C[m0:,n0:] (+)= A @ W^T + bias, one 128x128 tile.
// GACT = runtime column guard active.
// =====================================================================
__device__ __forceinline__ void gemm_tile(
    const float* __restrict__ A, int lda,
    const float* __restrict__ W, int ldw,
    const float* __restrict__ bias,
    float* __restrict__ C, int ldc,
    int N, int K, int m0, int n0, bool gact, float* sm)
{
    const int REGB = 128 * LDSB;
    bf16* base = reinterpret_cast<bf16*>(sm);
    bf16* AH = base;
    bf16* AL = base + 2 * REGB;
    bf16* WH = base + 4 * REGB;
    bf16* WL = base + 6 * REGB;

    int tid = threadIdx.x;
    int wid = tid >> 5;
    int wr = (wid & 3) * 32;
    int wc = (wid >> 2) * 64;
    int lrow = tid >> 1;
    int lc0  = (tid & 1) * 16;

    const float* pAg = A + (size_t)(m0 + lrow) * lda + lc0;
    const float* pWg = W + (size_t)(n0 + lrow) * ldw + lc0;
    bool wvalid = !gact || (n0 + lrow) < N;

    wmma::fragment<wmma::accumulator, 16, 16, 16, float> acc[2][4];
    #pragma unroll
    for (int i = 0; i < 2; i++)
        #pragma unroll
        for (int j = 0; j < 4; j++) wmma::fill_fragment(acc[i][j], 0.f);

    float ra[16], rw[16];
    int soff = lrow * LDSB + lc0;

    {
        ld16(ra, pAg);
        if (wvalid) ld16(rw, pWg); else zero16(rw);
        st_split16(AH + soff, AL + soff, ra);
        st_split16(WH + soff, WL + soff, rw);
    }
    __syncthreads();

    int nt = K / BKT;
    for (int t = 0; t < nt; t++) {
        int b = (t & 1) * REGB;
        if (t + 1 < nt) {
            int k0 = (t + 1) * BKT;
            ld16(ra, pAg + k0);
            if (wvalid) ld16(rw, pWg + k0); else zero16(rw);
        }

        #pragma unroll
        for (int kk = 0; kk < BKT; kk += 16) {
            wmma::fragment<wmma::matrix_a, 16, 16, 16, bf16, wmma::row_major> ah[2], al[2];
            wmma::fragment<wmma::matrix_b, 16, 16, 16, bf16, wmma::col_major> bh[4], bl[4];
            #pragma unroll
            for (int i = 0; i < 2; i++) {
                wmma::load_matrix_sync(ah[i], AH + b + (wr + i * 16) * LDSB + kk, LDSB);
                wmma::load_matrix_sync(al[i], AL + b + (wr + i * 16) * LDSB + kk, LDSB);
            }
            #pragma unroll
            for (int j = 0; j < 4; j++) {
                wmma::load_matrix_sync(bh[j], WH + b + (wc + j * 16) * LDSB + kk, LDSB);
                wmma::load_matrix_sync(bl[j], WL + b + (wc + j * 16) * LDSB + kk, LDSB);
            }
            #pragma unroll
            for (int i = 0; i < 2; i++)
                #pragma unroll
                for (int j = 0; j < 4; j++) {
                    wmma::mma_sync(acc[i][j], ah[i], bh[j], acc[i][j]);
                    wmma::mma_sync(acc[i][j], al[i], bh[j], acc[i][j]);
                    wmma::mma_sync(acc[i][j], ah[i], bl[j], acc[i][j]);
                }
        }

        if (t + 1 < nt) {
            int nb = ((t + 1) & 1) * REGB;
            st_split16(AH + nb + soff, AL + nb + soff, ra);
            st_split16(WH + nb + soff, WL + nb + soff, rw);
        }
        __syncthreads();
    }

    float* stg = sm;
    #pragma unroll
    for (int i = 0; i < 2; i++)
        #pragma unroll
        for (int j = 0; j < 4; j++)
            wmma::store_matrix_sync(stg + (wr + i * 16) * STG_LD + wc + j * 16,
                                    acc[i][j], STG_LD, wmma::mem_row_major);
    __syncthreads();

    int c4 = tid & 31;
    int col = n0 + c4 * 4;
    float4 bv = make_float4(0.f, 0.f, 0.f, 0.f);
    bool cfull = !gact || col + 3 < N;
    if (cfull) {
        bv.x = bias[col]; bv.y = bias[col + 1];
        bv.z = bias[col + 2]; bv.w = bias[col + 3];
    }
    #pragma unroll
    for (int rr = 0; rr < 16; rr++) {
        int row = (tid >> 5) + rr * 8;
        float4 v = *reinterpret_cast<float4*>(stg + row * STG_LD + c4 * 4);
        if (cfull) {
            v.x += bv.x; v.y += bv.y; v.z += bv.z; v.w += bv.w;
            *reinterpret_cast<float4*>(C + (size_t)(m0 + row) * ldc + col) = v;
        } else {
            float vv[4] = {v.x, v.y, v.z, v.w};
            #pragma unroll
            for (int e = 0; e < 4; e++)
                if (col + e < N)
                    C[(size_t)(m0 + row) * ldc + col + e] = vv[e] + bias[col + e];
        }
    }
}

// single-output GEMM (used for wo)
__global__ __launch_bounds__(256)
void gemmb_nt(const float* __restrict__ A, int lda,
              const float* __restrict__ W, int ldw,
              const float* __restrict__ bias,
              float* __restrict__ C, int ldc,
              int N, int K)
{
    extern __shared__ float sm[];
    gemm_tile(A, lda, W, ldw, bias, C, ldc, N, K,
              blockIdx.y * 128, blockIdx.x * 128, false, sm);
}

// dual-output GEMM: blocks [0,split) -> set 1, [split, ...) -> set 2
template <bool NG2>
__global__ __launch_bounds__(256)
void dual_gemm(const float* __restrict__ A1, int lda1,
               const float* __restrict__ W1, int ldw1,
               const float* __restrict__ b1,
               float* __restrict__ C1, int ldc1, int N1,
               const float* __restrict__ A2, int lda2,
               const float* __restrict__ W2, int ldw2,
               const float* __restrict__ b2,
               float* __restrict__ C2, int ldc2, int N2,
               int split, int K)
{
    extern __shared__ float sm[];
    bool two = (int)blockIdx.x >= split;
    int m0 = blockIdx.y * 128;
    if (!two) {
        gemm_tile(A1, lda1, W1, ldw1, b1, C1, ldc1, N1, K,
                  m0, blockIdx.x * 128, false, sm);
    } else {
        gemm_tile(A2, lda2, W2, ldw2, b2, C2, ldc2, N2, K,
                  m0, (blockIdx.x - split) * 128, NG2, sm);
    }
}

// =====================================================================
// Fused flash attention (identical to R9 passing version)
// =====================================================================
__global__ __launch_bounds__(256)
void flash_attn(const float* __restrict__ q,
                const float* __restrict__ kvb,
                const float* __restrict__ kpe,
                float* __restrict__ att)
{
    extern __shared__ char smemc[];
    bf16*  QH = (bf16*)(smemc + OFF_QH);
    bf16*  QL = (bf16*)(smemc + OFF_QL);
    bf16*  KH = (bf16*)(smemc + OFF_KH);
    bf16*  KL = (bf16*)(smemc + OFF_KL);
    bf16*  VH = (bf16*)(smemc + OFF_VH);
    bf16*  VL = (bf16*)(smemc + OFF_VL);
    float* S  = (float*)(smemc + OFF_S);
    bf16*  PH = (bf16*)(smemc + OFF_S);
    bf16*  PL = (bf16*)(smemc + OFF_PL);
    float* O  = (float*)(smemc + OFF_O);
    float* mv = (float*)(smemc + OFF_M);
    float* lv = (float*)(smemc + OFF_L);
    float* cvv= (float*)(smemc + OFF_C);

    int h  = blockIdx.x;
    int mq = gridDim.y - 1 - blockIdx.y;
    int m0 = mq * FBM;
    int tid = threadIdx.x;
    int wid = tid >> 5;
    int r4  = tid >> 2;
    int q4  = tid & 3;

    #pragma unroll
    for (int it = 0; it < 3; it++) {
        int col = q4 * 16 + it * 64;
        float rr[16];
        ld16(rr, q + (size_t)(m0 + r4) * QW + h * QKHD + col);
        #pragma unroll
        for (int i = 0; i < 16; i++) rr[i] *= ATTN_SCALE;
        st_split16(QH + r4 * FQS + col, QL + r4 * FQS + col, rr);
    }
    for (int i = tid; i < FBM * FVS; i += 256) O[i] = 0.f;
    if (tid < FBM) { mv[tid] = -INFINITY; lv[tid] = 0.f; }
    __syncthreads();

    for (int jt = 0; jt <= mq; jt++) {
        int j0 = jt * FBN;

        #pragma unroll
        for (int it = 0; it < 3; it++) {
            int col = q4 * 16 + it * 64;
            const float* src = (col < NOPE)
                ? (kvb + (size_t)(j0 + r4) * KVBW + h * (NOPE + VHD) + col)
                : (kpe + (size_t)(j0 + r4) * ROPED + (col - NOPE));
            float rr[16];
            ld16(rr, src);
            st_split16(KH + r4 * FQS + col, KL + r4 * FQS + col, rr);
        }
        #pragma unroll
        for (int it = 0; it < 2; it++) {
            int col = q4 * 16 + it * 64;
            float rr[16];
            ld16(rr, kvb + (size_t)(j0 + r4) * KVBW + h * (NOPE + VHD) + NOPE + col);
            st_split16(VH + r4 * FVS + col, VL + r4 * FVS + col, rr);
        }
        __syncthreads();

        {
            int wr = (wid >> 1) * 16;
            int wc = (wid & 1) * 32;
            wmma::fragment<wmma::accumulator, 16, 16, 16, float> sacc[2];
            #pragma unroll
            for (int j = 0; j < 2; j++) wmma::fill_fragment(sacc[j], 0.f);
            #pragma unroll
            for (int kk = 0; kk < QKHD; kk += 16) {
                wmma::fragment<wmma::matrix_a, 16, 16, 16, bf16, wmma::row_major> ah, al;
                wmma::fragment<wmma::matrix_b, 16, 16, 16, bf16, wmma::col_major> bh, bl;
                wmma::load_matrix_sync(ah, QH + wr * FQS + kk, FQS);
                wmma::load_matrix_sync(al, QL + wr * FQS + kk, FQS);
                #pragma unroll
                for (int j = 0; j < 2; j++) {
                    wmma::load_matrix_sync(bh, KH + (wc + j * 16) * FQS + kk, FQS);
                    wmma::load_matrix_sync(bl, KL + (wc + j * 16) * FQS + kk, FQS);
                    wmma::mma_sync(sacc[j], ah, bh, sacc[j]);
                    wmma::mma_sync(sacc[j], al, bh, sacc[j]);
                    wmma::mma_sync(sacc[j], ah, bl, sacc[j]);
                }
            }
            #pragma unroll
            for (int j = 0; j < 2; j++)
                wmma::store_matrix_sync(S + wr * FSS + wc + j * 16, sacc[j],
                                        FSS, wmma::mem_row_major);
        }
        __syncthreads();

        float p[16];
        {
            bool diag = (jt == mq);
            float s[16];
            const float* Sr = S + r4 * FSS + q4 * 16;
            #pragma unroll
            for (int i = 0; i < 16; i++) s[i] = Sr[i];
            if (diag) {
                #pragma unroll
                for (int i = 0; i < 16; i++)
                    if (q4 * 16 + i > r4) s[i] = -INFINITY;
            }
            float rmax = s[0];
            #pragma unroll
            for (int i = 1; i < 16; i++) rmax = fmaxf(rmax, s[i]);
            rmax = fmaxf(rmax, __shfl_xor_sync(0xffffffffu, rmax, 1));
            rmax = fmaxf(rmax, __shfl_xor_sync(0xffffffffu, rmax, 2));
            float mo = mv[r4];
            float mn = fmaxf(mo, rmax);
            float ps = 0.f;
            #pragma unroll
            for (int i = 0; i < 16; i++) { p[i] = __expf(s[i] - mn); ps += p[i]; }
            ps += __shfl_xor_sync(0xffffffffu, ps, 1);
            ps += __shfl_xor_sync(0xffffffffu, ps, 2);
            float c = __expf(mo - mn);
            if (q4 == 0) {
                mv[r4] = mn;
                lv[r4] = c * lv[r4] + ps;
                cvv[r4] = c;
            }
        }
        __syncthreads();

        st_split16(PH + r4 * FSS + q4 * 16, PL + r4 * FSS + q4 * 16, p);
        {
            float c = cvv[r4];
            float4* Or = reinterpret_cast<float4*>(O + r4 * FVS + q4 * 32);
            #pragma unroll
            for (int i = 0; i < 8; i++) {
                float4 v = Or[i];
                v.x *= c; v.y *= c; v.z *= c; v.w *= c;
                Or[i] = v;
            }
        }
        __syncthreads();

        {
            int wr = (wid >> 1) * 16;
            int wc = (wid & 1) * 64;
            wmma::fragment<wmma::accumulator, 16, 16, 16, float> oacc[4];
            #pragma unroll
            for (int j = 0; j < 4; j++)
                wmma::load_matrix_sync(oacc[j], O + wr * FVS + wc + j * 16,
                                       FVS, wmma::mem_row_major);
            #pragma unroll
            for (int kk = 0; kk < FBN; kk += 16) {
                wmma::fragment<wmma::matrix_a, 16, 16, 16, bf16, wmma::row_major> pa, pl2;
                wmma::fragment<wmma::matrix_b, 16, 16, 16, bf16, wmma::row_major> vb, vbl;
                wmma::load_matrix_sync(pa,  PH + wr * FSS + kk, FSS);
                wmma::load_matrix_sync(pl2, PL + wr * FSS + kk, FSS);
                #pragma unroll
                for (int j = 0; j < 4; j++) {
                    wmma::load_matrix_sync(vb,  VH + kk * FVS + wc + j * 16, FVS);
                    wmma::load_matrix_sync(vbl, VL + kk * FVS + wc + j * 16, FVS);
                    wmma::mma_sync(oacc[j], pa,  vb,  oacc[j]);
                    wmma::mma_sync(oacc[j], pl2, vb,  oacc[j]);
                    wmma::mma_sync(oacc[j], pa,  vbl, oacc[j]);
                }
            }
            #pragma unroll
            for (int j = 0; j < 4; j++)
                wmma::store_matrix_sync(O + wr * FVS + wc + j * 16, oacc[j],
                                        FVS, wmma::mem_row_major);
        }
        __syncthreads();
    }

    {
        float inv = 1.f / lv[r4];
        const float4* Or = reinterpret_cast<const float4*>(O + r4 * FVS + q4 * 32);
        float4* outp = reinterpret_cast<float4*>(
            att + (size_t)(m0 + r4) * (NH * VHD) + h * VHD + q4 * 32);
        #pragma unroll
        for (int i = 0; i < 8; i++) {
            float4 v = Or[i];
            v.x *= inv; v.y *= inv; v.z *= inv; v.w *= inv;
            outp[i] = v;
        }
    }
}

// ---------------- merged norm: y==0 -> rmsnorm(qa); y==1 -> kv norm+rope ----
__global__ void norm_both(float* __restrict__ qa, const float* __restrict__ q_nw,
                          const float* __restrict__ kv, const float* __restrict__ kv_nw,
                          const float* __restrict__ cosT, const float* __restrict__ sinT,
                          float* __restrict__ kvn, float* __restrict__ kpe)
{
    int s = blockIdx.x;
    if (blockIdx.y == 0) {
        float* xr = qa + (size_t)s * QLR;
        float ss = 0.f;
        for (int i = threadIdx.x; i < QLR; i += blockDim.x) { float v = xr[i]; ss += v * v; }
        ss = blockReduceSum(ss);
        float rinv = rsqrtf(ss / QLR + EPSV);
        for (int i = threadIdx.x; i < QLR; i += blockDim.x) xr[i] = xr[i] * rinv * q_nw[i];
    } else {
        const float* kr = kv + (size_t)s * (KVLR + ROPED);
        float ss = 0.f;
        for (int i = threadIdx.x; i < KVLR; i += blockDim.x) { float v = kr[i]; ss += v * v; }
        ss = blockReduceSum(ss);
        float rinv = rsqrtf(ss / KVLR + EPSV);
        for (int i = threadIdx.x; i < KVLR; i += blockDim.x)
            kvn[(size_t)s * KVLR + i] = kr[i] * rinv * kv_nw[i];
        if (threadIdx.x < ROPED / 2) {
            int i = threadIdx.x;
            float x0 = kr[KVLR + 2 * i], x1 = kr[KVLR + 2 * i + 1];
            float c = cosT[s * (ROPED / 2) + i], sn = sinT[s * (ROPED / 2) + i];
            kpe[(size_t)s * ROPED + 2 * i]     = x0 * c - x1 * sn;
            kpe[(size_t)s * ROPED + 2 * i + 1] = x0 * sn + x1 * c;
        }
    }
}

// ---------------- rope on q_pe ----------------
__global__ void rope_q(float* __restrict__ q, const float* __restrict__ cosT,
                       const float* __restrict__ sinT)
{
    int s = blockIdx.x;
    int h = threadIdx.x >> 5;
    int i = threadIdx.x & 31;
    float* p = q + (size_t)s * QW + h * QKHD + NOPE + 2 * i;
    float x0 = p[0], x1 = p[1];
    float c = cosT[s * (ROPED / 2) + i], sn = sinT[s * (ROPED / 2) + i];
    p[0] = x0 * c - x1 * sn;
    p[1] = x0 * sn + x1 * c;
}

// =====================================================================
extern "C" void kernel_launch(void* const* d_in, const int* in_sizes, int n_in,
                              void* d_out, int out_size)
{
    const float* x       = (const float*)d_in[0];
    const float* cosT    = (const float*)d_in[2];
    const float* sinT    = (const float*)d_in[3];
    const float* wq_a_w  = (const float*)d_in[5];
    const float* wq_a_b  = (const float*)d_in[6];
    const float* q_nw    = (const float*)d_in[7];
    const float* wq_b_w  = (const float*)d_in[8];
    const float* wq_b_b  = (const float*)d_in[9];
    const float* wkv_a_w = (const float*)d_in[10];
    const float* wkv_a_b = (const float*)d_in[11];
    const float* kv_nw   = (const float*)d_in[12];
    const float* wkv_b_w = (const float*)d_in[13];
    const float* wkv_b_b = (const float*)d_in[14];
    const float* wo_w    = (const float*)d_in[15];
    const float* wo_b    = (const float*)d_in[16];
    float* out = (float*)d_out;

    float *qa, *q, *kv, *kvn, *kpe, *kvb, *att;
    cudaGetSymbolAddress((void**)&qa,  g_qa);
    cudaGetSymbolAddress((void**)&q,   g_q);
    cudaGetSymbolAddress((void**)&kv,  g_kv);
    cudaGetSymbolAddress((void**)&kvn, g_kvn);
    cudaGetSymbolAddress((void**)&kpe, g_kpe);
    cudaGetSymbolAddress((void**)&kvb, g_kvb);
    cudaGetSymbolAddress((void**)&att, g_att);

    cudaFuncSetAttribute(gemmb_nt,        cudaFuncAttributeMaxDynamicSharedMemorySize, GEMM_SMEM);
    cudaFuncSetAttribute(dual_gemm<true>, cudaFuncAttributeMaxDynamicSharedMemorySize, GEMM_SMEM);
    cudaFuncSetAttribute(dual_gemm<false>,cudaFuncAttributeMaxDynamicSharedMemorySize, GEMM_SMEM);
    cudaFuncSetAttribute(flash_attn,      cudaFuncAttributeMaxDynamicSharedMemorySize, FLASH_SMEM);

    // ---- stage A: q_a + kv_a fused into one 144-CTA wave ----
    // set1: qa = x @ wq_a^T + b (N=512, 4 col-blocks)
    // set2: kv = x @ wkv_a^T + b (N=576, 5 col-blocks, guarded)
    dual_gemm<true><<<dim3(9, SEQ / 128), 256, GEMM_SMEM>>>(
        x, DIMM, wq_a_w, DIMM, wq_a_b, qa, QLR, QLR,
        x, DIMM, wkv_a_w, DIMM, wkv_a_b, kv, KVLR + ROPED, KVLR + ROPED,
        4, DIMM);

    // ---- stage B: both norms in one launch ----
    norm_both<<<dim3(SEQ, 2), 256>>>(qa, q_nw, kv, kv_nw, cosT, sinT, kvn, kpe);

    // ---- stage C: q_b + kv_b fused (both K=512) ----
    // set1: q = qa @ wq_b^T + b (N=3072, 24 col-blocks)
    // set2: kvb = kvn @ wkv_b^T + b (N=4096, 32 col-blocks)
    dual_gemm<false><<<dim3(56, SEQ / 128), 256, GEMM_SMEM>>>(
        qa, QLR, wq_b_w, QLR, wq_b_b, q, QW, QW,
        kvn, KVLR, wkv_b_w, KVLR, wkv_b_b, kvb, KVBW, KVBW,
        24, QLR);

    // ---- rope on q ----
    rope_q<<<SEQ, NH * 32>>>(q, cosT, sinT);

    // ---- fused flash attention ----
    flash_attn<<<dim3(NH, SEQ / FBM), 256, FLASH_SMEM>>>(q, kvb, kpe, att);

    // ---- out = att @ wo^T + b ----
    gemmb_nt<<<dim3(DIMM / 128, SEQ / 128), 256, GEMM_SMEM>>>(
        att, NH * VHD, wo_w, NH * VHD, wo_b, out, DIMM, DIMM, NH * VHD);
}